// round 3
// baseline (speedup 1.0000x reference)
#include <cuda_runtime.h>

// CustomStellarEncoder: Linear+BN+ReLU -> SAGEConv(mean) -> BN
// N=100000 nodes, E=3200000 edges, D_IN=256, HID=128.
// Output = concat(feat [N,128], out_feat [N,128]) fp32.

#define D_IN 256
#define HID 128
#define EPS 1e-5f
#define N_MAX 100000
#define USE_VEC_RED 1

#define BM 64
#define BK 32
#define GEMM_THREADS 256

// ---------------- scratch (device globals: allocation-guard safe) ----------------
__device__ float g_y1[(size_t)N_MAX * HID];    // pre-BN linear1 output
__device__ float g_msg[(size_t)N_MAX * HID];   // scattered message sums
__device__ float g_y2[(size_t)N_MAX * HID];    // pre-BN conv output
__device__ float g_deg[N_MAX];
__device__ float g_sum[2][HID];
__device__ float g_sumsq[2][HID];
__device__ float g_scale[2][HID];
__device__ float g_shift[2][HID];

// ---------------- zero scratch that is accumulated into ----------------
__global__ void zero_kernel(int n) {
    int i = blockIdx.x * blockDim.x + threadIdx.x;
    int m4 = n * (HID / 4);
    if (i < m4) ((float4*)g_msg)[i] = make_float4(0.f, 0.f, 0.f, 0.f);
    int j = i - m4;
    if (j >= 0 && j < n) g_deg[j] = 0.f;
    if (i < 2 * HID) {
        (&g_sum[0][0])[i] = 0.f;
        (&g_sumsq[0][0])[i] = 0.f;
    }
}

// ---------------- GEMM1: y1 = x @ W1 + b1   (N x 256) @ (256 x 128) ----------------
__global__ __launch_bounds__(GEMM_THREADS) void gemm1_kernel(
        const float* __restrict__ x, const float* __restrict__ W1,
        const float* __restrict__ b1, int n) {
    __shared__ __align__(16) float Ws[BK][HID];
    __shared__ __align__(16) float Xs[BK][BM + 4];

    int tid = threadIdx.x;
    int row0 = blockIdx.x * BM;
    int ty = tid >> 4, tx = tid & 15;
    int r0 = ty * 4, c0 = tx * 8;

    float acc[4][8];
#pragma unroll
    for (int i = 0; i < 4; i++)
#pragma unroll
        for (int j = 0; j < 8; j++) acc[i][j] = 0.f;

    for (int k0 = 0; k0 < D_IN; k0 += BK) {
        // load W chunk: BK x HID = 1024 float4
#pragma unroll
        for (int l = 0; l < 4; l++) {
            int li = tid + l * 256;
            int wr = li >> 5;            // 32 float4 per row
            int wc = (li & 31) << 2;
            *(float4*)&Ws[wr][wc] = *(const float4*)&W1[(k0 + wr) * HID + wc];
        }
        // load X chunk: BM x BK = 512 float4, stored transposed
#pragma unroll
        for (int l = 0; l < 2; l++) {
            int li = tid + l * 256;
            int xr = li >> 3;            // 8 float4 per row (BK/4)
            int xc = (li & 7) << 2;
            int row = row0 + xr;
            float4 v = make_float4(0.f, 0.f, 0.f, 0.f);
            if (row < n) v = *(const float4*)&x[row * D_IN + k0 + xc];
            Xs[xc + 0][xr] = v.x;
            Xs[xc + 1][xr] = v.y;
            Xs[xc + 2][xr] = v.z;
            Xs[xc + 3][xr] = v.w;
        }
        __syncthreads();
#pragma unroll 8
        for (int kk = 0; kk < BK; kk++) {
            float4 xv  = *(float4*)&Xs[kk][r0];
            float4 w0  = *(float4*)&Ws[kk][c0];
            float4 w1v = *(float4*)&Ws[kk][c0 + 4];
            float xr4[4] = {xv.x, xv.y, xv.z, xv.w};
            float wc8[8] = {w0.x, w0.y, w0.z, w0.w, w1v.x, w1v.y, w1v.z, w1v.w};
#pragma unroll
            for (int i = 0; i < 4; i++)
#pragma unroll
                for (int j = 0; j < 8; j++)
                    acc[i][j] += xr4[i] * wc8[j];
        }
        __syncthreads();
    }
    float4 bias0 = *(const float4*)&b1[c0];
    float4 bias1 = *(const float4*)&b1[c0 + 4];
#pragma unroll
    for (int i = 0; i < 4; i++) {
        int row = row0 + r0 + i;
        if (row < n) {
            float4 o0 = make_float4(acc[i][0] + bias0.x, acc[i][1] + bias0.y,
                                    acc[i][2] + bias0.z, acc[i][3] + bias0.w);
            float4 o1 = make_float4(acc[i][4] + bias1.x, acc[i][5] + bias1.y,
                                    acc[i][6] + bias1.z, acc[i][7] + bias1.w);
            *(float4*)&g_y1[row * HID + c0] = o0;
            *(float4*)&g_y1[row * HID + c0 + 4] = o1;
        }
    }
}

// ---------------- BN column stats (sum, sumsq) ----------------
__global__ void bn_stats_kernel(int which, int n, int s) {
    const float* __restrict__ in = which ? g_y2 : g_y1;
    int c = threadIdx.x;                  // 128 threads, one column each
    int r0 = blockIdx.x * 256;
    int rend = min(r0 + 256, n);
    float sum = 0.f, sq = 0.f;
#pragma unroll 4
    for (int r = r0; r < rend; r++) {
        float v = in[r * HID + c];
        sum += v;
        sq += v * v;
    }
    atomicAdd(&g_sum[s][c], sum);
    atomicAdd(&g_sumsq[s][c], sq);
}

// ---------------- fold BN into per-column scale/shift ----------------
__global__ void bn_finalize_kernel(const float* __restrict__ gamma,
                                   const float* __restrict__ beta, int n, int s) {
    int c = threadIdx.x;
    float invN = 1.0f / (float)n;
    float mu  = g_sum[s][c] * invN;
    float var = g_sumsq[s][c] * invN - mu * mu;
    float sc  = rsqrtf(var + EPS) * gamma[c];
    g_scale[s][c] = sc;
    g_shift[s][c] = beta[c] - mu * sc;
}

// ---------------- apply BN (+optional ReLU), float4 ----------------
__global__ void bn_apply_kernel(int which, float* __restrict__ out,
                                int n4, int s, int relu) {
    const float* __restrict__ in = which ? g_y2 : g_y1;
    int i = blockIdx.x * blockDim.x + threadIdx.x;
    if (i >= n4) return;
    int c = (i << 2) & (HID - 1);
    float4 v  = ((const float4*)in)[i];
    float4 sc = *(const float4*)&g_scale[s][c];
    float4 sh = *(const float4*)&g_shift[s][c];
    v.x = v.x * sc.x + sh.x;
    v.y = v.y * sc.y + sh.y;
    v.z = v.z * sc.z + sh.z;
    v.w = v.w * sc.w + sh.w;
    if (relu) {
        v.x = fmaxf(v.x, 0.f);
        v.y = fmaxf(v.y, 0.f);
        v.z = fmaxf(v.z, 0.f);
        v.w = fmaxf(v.w, 0.f);
    }
    ((float4*)out)[i] = v;
}

// ---------------- scatter: msg[dst] += feat[src]; also counts degree ----------------
__global__ void scatter_kernel(const int* __restrict__ ei,
                               const float* __restrict__ feat, int E_) {
    int t = blockIdx.x * blockDim.x + threadIdx.x;
    if (t >= E_ * 32) return;            // 32 float4 groups per edge
    int e = t >> 5;
    int g = t & 31;
    int c = g << 2;
    int srcn = ei[e];
    int dstn = ei[E_ + e];
    float4 v = *(const float4*)&feat[srcn * HID + c];
    float* p = &g_msg[dstn * HID + c];
#if USE_VEC_RED
    asm volatile("red.global.add.v4.f32 [%0], {%1, %2, %3, %4};"
                 :: "l"(p), "f"(v.x), "f"(v.y), "f"(v.z), "f"(v.w)
                 : "memory");
#else
    atomicAdd(p + 0, v.x);
    atomicAdd(p + 1, v.y);
    atomicAdd(p + 2, v.z);
    atomicAdd(p + 3, v.w);
#endif
    if (g == 0) {
        atomicAdd(&g_deg[dstn], 1.0f);
    }
}

// ---------------- GEMM2: y2 = [msg/deg | feat] @ [Wl ; Wr] + bl ----------------
__global__ __launch_bounds__(GEMM_THREADS) void gemm2_kernel(
        const float* __restrict__ feat, const float* __restrict__ Wl,
        const float* __restrict__ Wr, const float* __restrict__ bl, int n) {
    __shared__ __align__(16) float Ws[BK][HID];
    __shared__ __align__(16) float Xs[BK][BM + 4];
    __shared__ float invd[BM];

    int tid = threadIdx.x;
    int row0 = blockIdx.x * BM;
    int ty = tid >> 4, tx = tid & 15;
    int r0 = ty * 4, c0 = tx * 8;

    if (tid < BM) {
        int row = row0 + tid;
        float d = (row < n) ? g_deg[row] : 1.f;
        invd[tid] = 1.0f / fmaxf(d, 1.0f);
    }

    float acc[4][8];
#pragma unroll
    for (int i = 0; i < 4; i++)
#pragma unroll
        for (int j = 0; j < 8; j++) acc[i][j] = 0.f;

    __syncthreads();   // invd visible before Xs loads use it

    for (int k0 = 0; k0 < 2 * HID; k0 += BK) {
        bool firstHalf = (k0 < HID);
        int kk0 = k0 & (HID - 1);
        const float* __restrict__ wsrc = firstHalf ? Wl : Wr;
#pragma unroll
        for (int l = 0; l < 4; l++) {
            int li = tid + l * 256;
            int wr = li >> 5;
            int wc = (li & 31) << 2;
            *(float4*)&Ws[wr][wc] = *(const float4*)&wsrc[(kk0 + wr) * HID + wc];
        }
#pragma unroll
        for (int l = 0; l < 2; l++) {
            int li = tid + l * 256;
            int xr = li >> 3;
            int xc = (li & 7) << 2;
            int row = row0 + xr;
            float4 v = make_float4(0.f, 0.f, 0.f, 0.f);
            if (row < n) {
                if (firstHalf) {
                    v = *(const float4*)&g_msg[row * HID + kk0 + xc];
                    float s = invd[xr];
                    v.x *= s; v.y *= s; v.z *= s; v.w *= s;
                } else {
                    v = *(const float4*)&feat[row * HID + kk0 + xc];
                }
            }
            Xs[xc + 0][xr] = v.x;
            Xs[xc + 1][xr] = v.y;
            Xs[xc + 2][xr] = v.z;
            Xs[xc + 3][xr] = v.w;
        }
        __syncthreads();
#pragma unroll 8
        for (int kk = 0; kk < BK; kk++) {
            float4 xv  = *(float4*)&Xs[kk][r0];
            float4 w0  = *(float4*)&Ws[kk][c0];
            float4 w1v = *(float4*)&Ws[kk][c0 + 4];
            float xr4[4] = {xv.x, xv.y, xv.z, xv.w};
            float wc8[8] = {w0.x, w0.y, w0.z, w0.w, w1v.x, w1v.y, w1v.z, w1v.w};
#pragma unroll
            for (int i = 0; i < 4; i++)
#pragma unroll
                for (int j = 0; j < 8; j++)
                    acc[i][j] += xr4[i] * wc8[j];
        }
        __syncthreads();
    }
    float4 bias0 = *(const float4*)&bl[c0];
    float4 bias1 = *(const float4*)&bl[c0 + 4];
#pragma unroll
    for (int i = 0; i < 4; i++) {
        int row = row0 + r0 + i;
        if (row < n) {
            float4 o0 = make_float4(acc[i][0] + bias0.x, acc[i][1] + bias0.y,
                                    acc[i][2] + bias0.z, acc[i][3] + bias0.w);
            float4 o1 = make_float4(acc[i][4] + bias1.x, acc[i][5] + bias1.y,
                                    acc[i][6] + bias1.z, acc[i][7] + bias1.w);
            *(float4*)&g_y2[row * HID + c0] = o0;
            *(float4*)&g_y2[row * HID + c0 + 4] = o1;
        }
    }
}

// ---------------- launch ----------------
extern "C" void kernel_launch(void* const* d_in, const int* in_sizes, int n_in,
                              void* d_out, int out_size) {
    const float* x   = (const float*)d_in[0];
    const int*   ei  = (const int*)d_in[1];
    const float* W1  = (const float*)d_in[2];
    const float* b1  = (const float*)d_in[3];
    const float* g1  = (const float*)d_in[4];
    const float* be1 = (const float*)d_in[5];
    const float* Wl  = (const float*)d_in[6];
    const float* bl  = (const float*)d_in[7];
    const float* Wr  = (const float*)d_in[8];
    const float* g2  = (const float*)d_in[9];
    const float* be2 = (const float*)d_in[10];

    int n  = in_sizes[0] / D_IN;
    int E_ = in_sizes[1] / 2;

    float* feat = (float*)d_out;                    // first half: feat
    float* out2 = feat + (size_t)n * HID;           // second half: out_feat

    int n4 = n * (HID / 4);

    // 1. zero accumulators
    {
        int zt = n4 + n;
        zero_kernel<<<(zt + 255) / 256, 256>>>(n);
    }
    // 2. linear1
    int gblocks = (n + BM - 1) / BM;
    gemm1_kernel<<<gblocks, GEMM_THREADS>>>(x, W1, b1, n);
    // 3-5. BN1 + ReLU -> feat
    int sblocks = (n + 255) / 256;
    bn_stats_kernel<<<sblocks, HID>>>(0, n, 0);
    bn_finalize_kernel<<<1, HID>>>(g1, be1, n, 0);
    bn_apply_kernel<<<(n4 + 255) / 256, 256>>>(0, feat, n4, 0, 1);
    // 6. scatter mean-aggregation numerator + degree count (fused)
    {
        long long total = (long long)E_ * 32;
        int blocks = (int)((total + 255) / 256);
        scatter_kernel<<<blocks, 256>>>(ei, feat, E_);
    }
    // 7. SAGE linear (fused lin_l + lin_r)
    gemm2_kernel<<<gblocks, GEMM_THREADS>>>(feat, Wl, Wr, bl, n);
    // 8-10. BN2 -> out_feat
    bn_stats_kernel<<<sblocks, HID>>>(1, n, 1);
    bn_finalize_kernel<<<1, HID>>>(g2, be2, n, 1);
    bn_apply_kernel<<<(n4 + 255) / 256, 256>>>(1, out2, n4, 1, 0);
}

// round 4
// speedup vs baseline: 2.0746x; 2.0746x over previous
#include <cuda_runtime.h>

// CustomStellarEncoder: Linear+BN+ReLU -> SAGEConv(mean) -> BN
// N=100000 nodes, E=3200000 edges, D_IN=256, HID=128.
// Output = concat(feat [N,128], out_feat [N,128]) fp32.
// R4: atomic scatter replaced by CSR build (count/scan/fill) + warp-per-node
//     segmented reduction (atomic-free aggregate, writes mean directly).

#define D_IN 256
#define HID 128
#define EPS 1e-5f
#define N_MAX 100000
#define E_MAX 3200000

#define BM 64
#define BK 32
#define GEMM_THREADS 256

// ---------------- scratch (device globals: allocation-guard safe) ----------------
__device__ float g_y1[(size_t)N_MAX * HID];    // pre-BN linear1 output
__device__ float g_msg[(size_t)N_MAX * HID];   // aggregated mean messages
__device__ float g_y2[(size_t)N_MAX * HID];    // pre-BN conv output
__device__ int   g_cnt[N_MAX];                 // per-dst degree counts
__device__ int   g_fill[N_MAX];                // fill cursors
__device__ int   g_rowstart[N_MAX + 1];        // CSR row offsets
__device__ int   g_srcsorted[E_MAX];           // src ids sorted by dst
__device__ int   g_bsum[128];                  // scan block partials
__device__ float g_sum[2][HID];
__device__ float g_sumsq[2][HID];
__device__ float g_scale[2][HID];
__device__ float g_shift[2][HID];

// ---------------- zero accumulators ----------------
__global__ void zero_kernel(int n) {
    int i = blockIdx.x * blockDim.x + threadIdx.x;
    if (i < n) {
        g_cnt[i] = 0;
        g_fill[i] = 0;
    }
    if (i < 2 * HID) {
        (&g_sum[0][0])[i] = 0.f;
        (&g_sumsq[0][0])[i] = 0.f;
    }
}

// ---------------- GEMM1: y1 = x @ W1 + b1   (N x 256) @ (256 x 128) ----------------
__global__ __launch_bounds__(GEMM_THREADS) void gemm1_kernel(
        const float* __restrict__ x, const float* __restrict__ W1,
        const float* __restrict__ b1, int n) {
    __shared__ __align__(16) float Ws[BK][HID];
    __shared__ __align__(16) float Xs[BK][BM + 4];

    int tid = threadIdx.x;
    int row0 = blockIdx.x * BM;
    int ty = tid >> 4, tx = tid & 15;
    int r0 = ty * 4, c0 = tx * 8;

    float acc[4][8];
#pragma unroll
    for (int i = 0; i < 4; i++)
#pragma unroll
        for (int j = 0; j < 8; j++) acc[i][j] = 0.f;

    for (int k0 = 0; k0 < D_IN; k0 += BK) {
#pragma unroll
        for (int l = 0; l < 4; l++) {
            int li = tid + l * 256;
            int wr = li >> 5;
            int wc = (li & 31) << 2;
            *(float4*)&Ws[wr][wc] = *(const float4*)&W1[(k0 + wr) * HID + wc];
        }
#pragma unroll
        for (int l = 0; l < 2; l++) {
            int li = tid + l * 256;
            int xr = li >> 3;
            int xc = (li & 7) << 2;
            int row = row0 + xr;
            float4 v = make_float4(0.f, 0.f, 0.f, 0.f);
            if (row < n) v = *(const float4*)&x[row * D_IN + k0 + xc];
            Xs[xc + 0][xr] = v.x;
            Xs[xc + 1][xr] = v.y;
            Xs[xc + 2][xr] = v.z;
            Xs[xc + 3][xr] = v.w;
        }
        __syncthreads();
#pragma unroll 8
        for (int kk = 0; kk < BK; kk++) {
            float4 xv  = *(float4*)&Xs[kk][r0];
            float4 w0  = *(float4*)&Ws[kk][c0];
            float4 w1v = *(float4*)&Ws[kk][c0 + 4];
            float xr4[4] = {xv.x, xv.y, xv.z, xv.w};
            float wc8[8] = {w0.x, w0.y, w0.z, w0.w, w1v.x, w1v.y, w1v.z, w1v.w};
#pragma unroll
            for (int i = 0; i < 4; i++)
#pragma unroll
                for (int j = 0; j < 8; j++)
                    acc[i][j] += xr4[i] * wc8[j];
        }
        __syncthreads();
    }
    float4 bias0 = *(const float4*)&b1[c0];
    float4 bias1 = *(const float4*)&b1[c0 + 4];
#pragma unroll
    for (int i = 0; i < 4; i++) {
        int row = row0 + r0 + i;
        if (row < n) {
            float4 o0 = make_float4(acc[i][0] + bias0.x, acc[i][1] + bias0.y,
                                    acc[i][2] + bias0.z, acc[i][3] + bias0.w);
            float4 o1 = make_float4(acc[i][4] + bias1.x, acc[i][5] + bias1.y,
                                    acc[i][6] + bias1.z, acc[i][7] + bias1.w);
            *(float4*)&g_y1[row * HID + c0] = o0;
            *(float4*)&g_y1[row * HID + c0 + 4] = o1;
        }
    }
}

// ---------------- BN column stats (sum, sumsq) ----------------
__global__ void bn_stats_kernel(int which, int n, int s) {
    const float* __restrict__ in = which ? g_y2 : g_y1;
    int c = threadIdx.x;
    int r0 = blockIdx.x * 256;
    int rend = min(r0 + 256, n);
    float sum = 0.f, sq = 0.f;
#pragma unroll 4
    for (int r = r0; r < rend; r++) {
        float v = in[r * HID + c];
        sum += v;
        sq += v * v;
    }
    atomicAdd(&g_sum[s][c], sum);
    atomicAdd(&g_sumsq[s][c], sq);
}

// ---------------- fold BN into per-column scale/shift ----------------
__global__ void bn_finalize_kernel(const float* __restrict__ gamma,
                                   const float* __restrict__ beta, int n, int s) {
    int c = threadIdx.x;
    float invN = 1.0f / (float)n;
    float mu  = g_sum[s][c] * invN;
    float var = g_sumsq[s][c] * invN - mu * mu;
    float sc  = rsqrtf(var + EPS) * gamma[c];
    g_scale[s][c] = sc;
    g_shift[s][c] = beta[c] - mu * sc;
}

// ---------------- apply BN (+optional ReLU), float4 ----------------
__global__ void bn_apply_kernel(int which, float* __restrict__ out,
                                int n4, int s, int relu) {
    const float* __restrict__ in = which ? g_y2 : g_y1;
    int i = blockIdx.x * blockDim.x + threadIdx.x;
    if (i >= n4) return;
    int c = (i << 2) & (HID - 1);
    float4 v  = ((const float4*)in)[i];
    float4 sc = *(const float4*)&g_scale[s][c];
    float4 sh = *(const float4*)&g_shift[s][c];
    v.x = v.x * sc.x + sh.x;
    v.y = v.y * sc.y + sh.y;
    v.z = v.z * sc.z + sh.z;
    v.w = v.w * sc.w + sh.w;
    if (relu) {
        v.x = fmaxf(v.x, 0.f);
        v.y = fmaxf(v.y, 0.f);
        v.z = fmaxf(v.z, 0.f);
        v.w = fmaxf(v.w, 0.f);
    }
    ((float4*)out)[i] = v;
}

// ---------------- CSR build: count ----------------
__global__ void count_kernel(const int* __restrict__ ei, int E_) {
    int e = blockIdx.x * blockDim.x + threadIdx.x;
    if (e < E_) atomicAdd(&g_cnt[ei[E_ + e]], 1);
}

// ---------------- CSR build: hierarchical exclusive scan ----------------
__global__ void scan1_kernel(int n) {
    __shared__ int s[1024];
    int i = blockIdx.x * 1024 + threadIdx.x;
    int v = (i < n) ? g_cnt[i] : 0;
    s[threadIdx.x] = v;
    __syncthreads();
#pragma unroll
    for (int off = 1; off < 1024; off <<= 1) {
        int t = (threadIdx.x >= off) ? s[threadIdx.x - off] : 0;
        __syncthreads();
        s[threadIdx.x] += t;
        __syncthreads();
    }
    if (i < n) g_rowstart[i] = s[threadIdx.x] - v;   // exclusive
    if (threadIdx.x == 1023) g_bsum[blockIdx.x] = s[1023];
}

__global__ void scan2_kernel(int nb, int n) {
    if (threadIdx.x == 0) {
        int acc = 0;
        for (int b = 0; b < nb; b++) {
            int t = g_bsum[b];
            g_bsum[b] = acc;
            acc += t;
        }
        g_rowstart[n] = acc;   // = total edges
    }
}

__global__ void scan3_kernel(int n) {
    int i = blockIdx.x * blockDim.x + threadIdx.x;
    if (i < n) g_rowstart[i] += g_bsum[i >> 10];
}

// ---------------- CSR build: fill src sorted by dst ----------------
__global__ void fill_kernel(const int* __restrict__ ei, int E_) {
    int e = blockIdx.x * blockDim.x + threadIdx.x;
    if (e >= E_) return;
    int dst = ei[E_ + e];
    int pos = atomicAdd(&g_fill[dst], 1);
    g_srcsorted[g_rowstart[dst] + pos] = ei[e];
}

// ---------------- aggregate: warp per dst node, write mean ----------------
__global__ __launch_bounds__(256) void aggregate_kernel(
        const float* __restrict__ feat, int n) {
    int w = (blockIdx.x * blockDim.x + threadIdx.x) >> 5;
    if (w >= n) return;
    int lane = threadIdx.x & 31;
    int beg = g_rowstart[w];
    int end = g_rowstart[w + 1];
    int c = lane << 2;

    float4 acc = make_float4(0.f, 0.f, 0.f, 0.f);
    int i = beg;
    for (; i + 4 <= end; i += 4) {
        int s0 = g_srcsorted[i];
        int s1 = g_srcsorted[i + 1];
        int s2 = g_srcsorted[i + 2];
        int s3 = g_srcsorted[i + 3];
        float4 v0 = *(const float4*)&feat[s0 * HID + c];
        float4 v1 = *(const float4*)&feat[s1 * HID + c];
        float4 v2 = *(const float4*)&feat[s2 * HID + c];
        float4 v3 = *(const float4*)&feat[s3 * HID + c];
        acc.x += v0.x + v1.x + v2.x + v3.x;
        acc.y += v0.y + v1.y + v2.y + v3.y;
        acc.z += v0.z + v1.z + v2.z + v3.z;
        acc.w += v0.w + v1.w + v2.w + v3.w;
    }
    for (; i < end; i++) {
        int s0 = g_srcsorted[i];
        float4 v0 = *(const float4*)&feat[s0 * HID + c];
        acc.x += v0.x;
        acc.y += v0.y;
        acc.z += v0.z;
        acc.w += v0.w;
    }
    float inv = 1.0f / fmaxf((float)(end - beg), 1.0f);
    acc.x *= inv;
    acc.y *= inv;
    acc.z *= inv;
    acc.w *= inv;
    *(float4*)&g_msg[w * HID + c] = acc;
}

// ---------------- GEMM2: y2 = [mean | feat] @ [Wl ; Wr] + bl ----------------
__global__ __launch_bounds__(GEMM_THREADS) void gemm2_kernel(
        const float* __restrict__ feat, const float* __restrict__ Wl,
        const float* __restrict__ Wr, const float* __restrict__ bl, int n) {
    __shared__ __align__(16) float Ws[BK][HID];
    __shared__ __align__(16) float Xs[BK][BM + 4];

    int tid = threadIdx.x;
    int row0 = blockIdx.x * BM;
    int ty = tid >> 4, tx = tid & 15;
    int r0 = ty * 4, c0 = tx * 8;

    float acc[4][8];
#pragma unroll
    for (int i = 0; i < 4; i++)
#pragma unroll
        for (int j = 0; j < 8; j++) acc[i][j] = 0.f;

    for (int k0 = 0; k0 < 2 * HID; k0 += BK) {
        bool firstHalf = (k0 < HID);
        int kk0 = k0 & (HID - 1);
        const float* __restrict__ wsrc = firstHalf ? Wl : Wr;
        const float* __restrict__ xsrc = firstHalf ? g_msg : feat;
#pragma unroll
        for (int l = 0; l < 4; l++) {
            int li = tid + l * 256;
            int wr = li >> 5;
            int wc = (li & 31) << 2;
            *(float4*)&Ws[wr][wc] = *(const float4*)&wsrc[(kk0 + wr) * HID + wc];
        }
#pragma unroll
        for (int l = 0; l < 2; l++) {
            int li = tid + l * 256;
            int xr = li >> 3;
            int xc = (li & 7) << 2;
            int row = row0 + xr;
            float4 v = make_float4(0.f, 0.f, 0.f, 0.f);
            if (row < n) v = *(const float4*)&xsrc[row * HID + kk0 + xc];
            Xs[xc + 0][xr] = v.x;
            Xs[xc + 1][xr] = v.y;
            Xs[xc + 2][xr] = v.z;
            Xs[xc + 3][xr] = v.w;
        }
        __syncthreads();
#pragma unroll 8
        for (int kk = 0; kk < BK; kk++) {
            float4 xv  = *(float4*)&Xs[kk][r0];
            float4 w0  = *(float4*)&Ws[kk][c0];
            float4 w1v = *(float4*)&Ws[kk][c0 + 4];
            float xr4[4] = {xv.x, xv.y, xv.z, xv.w};
            float wc8[8] = {w0.x, w0.y, w0.z, w0.w, w1v.x, w1v.y, w1v.z, w1v.w};
#pragma unroll
            for (int i = 0; i < 4; i++)
#pragma unroll
                for (int j = 0; j < 8; j++)
                    acc[i][j] += xr4[i] * wc8[j];
        }
        __syncthreads();
    }
    float4 bias0 = *(const float4*)&bl[c0];
    float4 bias1 = *(const float4*)&bl[c0 + 4];
#pragma unroll
    for (int i = 0; i < 4; i++) {
        int row = row0 + r0 + i;
        if (row < n) {
            float4 o0 = make_float4(acc[i][0] + bias0.x, acc[i][1] + bias0.y,
                                    acc[i][2] + bias0.z, acc[i][3] + bias0.w);
            float4 o1 = make_float4(acc[i][4] + bias1.x, acc[i][5] + bias1.y,
                                    acc[i][6] + bias1.z, acc[i][7] + bias1.w);
            *(float4*)&g_y2[row * HID + c0] = o0;
            *(float4*)&g_y2[row * HID + c0 + 4] = o1;
        }
    }
}

// ---------------- launch ----------------
extern "C" void kernel_launch(void* const* d_in, const int* in_sizes, int n_in,
                              void* d_out, int out_size) {
    const float* x   = (const float*)d_in[0];
    const int*   ei  = (const int*)d_in[1];
    const float* W1  = (const float*)d_in[2];
    const float* b1  = (const float*)d_in[3];
    const float* g1  = (const float*)d_in[4];
    const float* be1 = (const float*)d_in[5];
    const float* Wl  = (const float*)d_in[6];
    const float* bl  = (const float*)d_in[7];
    const float* Wr  = (const float*)d_in[8];
    const float* g2  = (const float*)d_in[9];
    const float* be2 = (const float*)d_in[10];

    int n  = in_sizes[0] / D_IN;
    int E_ = in_sizes[1] / 2;

    float* feat = (float*)d_out;                    // first half: feat
    float* out2 = feat + (size_t)n * HID;           // second half: out_feat

    int n4 = n * (HID / 4);
    int eblocks = (E_ + 255) / 256;
    int nblocks = (n + 255) / 256;
    int nb1024 = (n + 1023) / 1024;

    // 1. zero accumulators
    zero_kernel<<<nblocks, 256>>>(n);
    // 2. linear1
    int gblocks = (n + BM - 1) / BM;
    gemm1_kernel<<<gblocks, GEMM_THREADS>>>(x, W1, b1, n);
    // 3-5. BN1 + ReLU -> feat
    bn_stats_kernel<<<nblocks, HID>>>(0, n, 0);
    bn_finalize_kernel<<<1, HID>>>(g1, be1, n, 0);
    bn_apply_kernel<<<(n4 + 255) / 256, 256>>>(0, feat, n4, 0, 1);
    // 6. CSR build
    count_kernel<<<eblocks, 256>>>(ei, E_);
    scan1_kernel<<<nb1024, 1024>>>(n);
    scan2_kernel<<<1, 32>>>(nb1024, n);
    scan3_kernel<<<nblocks, 256>>>(n);
    fill_kernel<<<eblocks, 256>>>(ei, E_);
    // 7. segmented mean aggregation (warp per node)
    aggregate_kernel<<<(n * 32 + 255) / 256, 256>>>(feat, n);
    // 8. SAGE linear (fused lin_l + lin_r)
    gemm2_kernel<<<gblocks, GEMM_THREADS>>>(feat, Wl, Wr, bl, n);
    // 9-11. BN2 -> out_feat
    bn_stats_kernel<<<nblocks, HID>>>(1, n, 1);
    bn_finalize_kernel<<<1, HID>>>(g2, be2, n, 1);
    bn_apply_kernel<<<(n4 + 255) / 256, 256>>>(1, out2, n4, 1, 0);
}

// round 8
// speedup vs baseline: 2.5325x; 1.2207x over previous
#include <cuda_runtime.h>
#include <cstdint>

// CustomStellarEncoder: Linear+BN+ReLU -> SAGEConv(mean) -> BN
// R6: GEMMs use warp-level mma.sync tf32 (baseline PTX, works at sm_103
//     target) with 3xTF32 hi/lo split for fp32 accuracy.
//     CSR + warp aggregate + BN pipeline unchanged from R4 (714us baseline).

#define D_IN 256
#define HID 128
#define EPS 1e-5f
#define N_MAX 100000
#define E_MAX 3200000

// ================= scratch =================
__device__ float g_y1[(size_t)N_MAX * HID];
__device__ float g_msg[(size_t)N_MAX * HID];
__device__ float g_y2[(size_t)N_MAX * HID];
__device__ int   g_cnt[N_MAX];
__device__ int   g_fill[N_MAX];
__device__ int   g_rowstart[N_MAX + 1];
__device__ int   g_srcsorted[E_MAX];
__device__ int   g_bsum[128];
__device__ float g_sum[2][HID];
__device__ float g_sumsq[2][HID];
__device__ float g_scale[2][HID];
__device__ float g_shift[2][HID];
// weight tf32 hi/lo images: [K=256][132] float2 (hi, lo), row stride 132
__device__ float2 g_w1b[256 * 132];
__device__ float2 g_w2b[256 * 132];

// ================= tf32 helpers =================
__device__ __forceinline__ uint32_t f2tf(float x) {
    uint32_t r;
    asm("cvt.rna.tf32.f32 %0, %1;" : "=r"(r) : "f"(x));
    return r;
}

__device__ __forceinline__ void mma_tf32(float* d, uint32_t a0, uint32_t a1,
                                         uint32_t a2, uint32_t a3,
                                         uint32_t b0, uint32_t b1) {
    asm volatile(
        "mma.sync.aligned.m16n8k8.row.col.f32.tf32.tf32.f32 "
        "{%0,%1,%2,%3}, {%4,%5,%6,%7}, {%8,%9}, {%0,%1,%2,%3};"
        : "+f"(d[0]), "+f"(d[1]), "+f"(d[2]), "+f"(d[3])
        : "r"(a0), "r"(a1), "r"(a2), "r"(a3), "r"(b0), "r"(b1));
}

// ================= weight image prep (tf32 hi/lo split) =================
// wset 0: W1 [256x128]; wset 1: rows 0-127 = Wl, rows 128-255 = Wr
__global__ void wprep_kernel(const float* __restrict__ W1,
                             const float* __restrict__ Wl,
                             const float* __restrict__ Wr) {
    int idx = blockIdx.x * blockDim.x + threadIdx.x;
    if (idx >= 2 * 256 * 128) return;
    int wset = idx >> 15;
    int rem  = idx & 32767;
    int k = rem >> 7;
    int nn = rem & 127;
    float v;
    if (wset == 0) v = W1[k * 128 + nn];
    else           v = (k < 128) ? Wl[k * 128 + nn] : Wr[(k - 128) * 128 + nn];
    uint32_t hi = f2tf(v);
    float hif = __uint_as_float(hi);
    uint32_t lo = f2tf(v - hif);
    float2 hl = make_float2(hif, __uint_as_float(lo));
    if (wset == 0) g_w1b[k * 132 + nn] = hl;
    else           g_w2b[k * 132 + nn] = hl;
}

// ================= tf32 GEMM: out[N x 128] = X[N x 256] @ W + bias =================
// mode 0: A row = x[row, 0:256] (stride 256), W = g_w1b, out = g_y1
// mode 1: A row = [g_msg[row] | feat[row]],   W = g_w2b, out = g_y2
#define A_STRIDE 68
#define B_STRIDE 132
#define SM_B_OFF 34816                       // 128*68*4 bytes
#define SM_GTOTAL (SM_B_OFF + 64 * 132 * 8)  // + 67584 = 102400

__global__ __launch_bounds__(256, 2) void tc_gemm_kernel(
        int mode, const float* __restrict__ xptr,
        const float* __restrict__ bias, int n) {
    extern __shared__ char smem[];
    float*  As = (float*)smem;                 // [128][68]
    float2* Bs = (float2*)(smem + SM_B_OFF);   // [64][132]

    int tid = threadIdx.x;
    int lane = tid & 31;
    int wid = tid >> 5;
    int row0 = blockIdx.x * 128;
    int wrow = wid * 16;

    float d[16][4];
#pragma unroll
    for (int t = 0; t < 16; t++)
#pragma unroll
        for (int q = 0; q < 4; q++) d[t][q] = 0.f;

    const float2* wimg = mode ? g_w2b : g_w1b;

    for (int c = 0; c < 4; c++) {
        int k0 = c * 64;
        // ---- load A chunk [128 rows x 64 cols] ----
        {
            int r = tid >> 1;
            int cb = (tid & 1) * 32;
            int grow = row0 + r;
            const float* src;
            if (mode == 0) {
                src = xptr + (size_t)grow * 256 + k0;
            } else {
                src = (k0 < 128 ? g_msg + (size_t)grow * 128 + k0
                                : xptr + (size_t)grow * 128 + (k0 - 128));
            }
            bool valid = grow < n;
#pragma unroll
            for (int j = 0; j < 8; j++) {
                float4 v = valid ? *(const float4*)(src + cb + j * 4)
                                 : make_float4(0.f, 0.f, 0.f, 0.f);
                *(float4*)&As[r * A_STRIDE + cb + j * 4] = v;
            }
        }
        // ---- load B chunk [64 k-rows x 132 float2] (contiguous copy) ----
        {
            const float4* src = (const float4*)(wimg + k0 * 132);
            float4* dst = (float4*)Bs;
            for (int i = tid; i < 4224; i += 256) dst[i] = src[i];
        }
        __syncthreads();

        // ---- compute: 8 k-steps of 8 ----
#pragma unroll
        for (int k8 = 0; k8 < 8; k8++) {
            int ar = wrow + (lane >> 2);
            int ac = k8 * 8 + (lane & 3);
            float a0 = As[ar * A_STRIDE + ac];
            float a1 = As[(ar + 8) * A_STRIDE + ac];
            float a2 = As[ar * A_STRIDE + ac + 4];
            float a3 = As[(ar + 8) * A_STRIDE + ac + 4];
            uint32_t ah0 = f2tf(a0), ah1 = f2tf(a1), ah2 = f2tf(a2), ah3 = f2tf(a3);
            uint32_t al0 = f2tf(a0 - __uint_as_float(ah0));
            uint32_t al1 = f2tf(a1 - __uint_as_float(ah1));
            uint32_t al2 = f2tf(a2 - __uint_as_float(ah2));
            uint32_t al3 = f2tf(a3 - __uint_as_float(ah3));
            int bk = k8 * 8 + (lane & 3);
            int bn = lane >> 2;
#pragma unroll
            for (int nt = 0; nt < 16; nt++) {
                float2 b0 = Bs[bk * B_STRIDE + nt * 8 + bn];
                float2 b1 = Bs[(bk + 4) * B_STRIDE + nt * 8 + bn];
                uint32_t bh0 = __float_as_uint(b0.x);
                uint32_t bl0 = __float_as_uint(b0.y);
                uint32_t bh1 = __float_as_uint(b1.x);
                uint32_t bl1 = __float_as_uint(b1.y);
                mma_tf32(d[nt], ah0, ah1, ah2, ah3, bh0, bh1);
                mma_tf32(d[nt], al0, al1, al2, al3, bh0, bh1);
                mma_tf32(d[nt], ah0, ah1, ah2, ah3, bl0, bl1);
            }
        }
        __syncthreads();
    }

    // ---- epilogue: add bias, store ----
    float* outp = mode ? g_y2 : g_y1;
    int r0 = row0 + wrow + (lane >> 2);
    int r1 = r0 + 8;
    bool v0 = r0 < n, v1 = r1 < n;
#pragma unroll
    for (int nt = 0; nt < 16; nt++) {
        int col = nt * 8 + 2 * (lane & 3);
        float bx = __ldg(&bias[col]);
        float by = __ldg(&bias[col + 1]);
        if (v0) *(float2*)&outp[(size_t)r0 * HID + col] =
            make_float2(d[nt][0] + bx, d[nt][1] + by);
        if (v1) *(float2*)&outp[(size_t)r1 * HID + col] =
            make_float2(d[nt][2] + bx, d[nt][3] + by);
    }
}

// ================= zero accumulators =================
__global__ void zero_kernel(int n) {
    int i = blockIdx.x * blockDim.x + threadIdx.x;
    if (i < n) {
        g_cnt[i] = 0;
        g_fill[i] = 0;
    }
    if (i < 2 * HID) {
        (&g_sum[0][0])[i] = 0.f;
        (&g_sumsq[0][0])[i] = 0.f;
    }
}

// ================= BN =================
__global__ void bn_stats_kernel(int which, int n, int s) {
    const float* __restrict__ in = which ? g_y2 : g_y1;
    int c = threadIdx.x;
    int r0 = blockIdx.x * 256;
    int rend = min(r0 + 256, n);
    float sum = 0.f, sq = 0.f;
#pragma unroll 4
    for (int r = r0; r < rend; r++) {
        float v = in[r * HID + c];
        sum += v;
        sq += v * v;
    }
    atomicAdd(&g_sum[s][c], sum);
    atomicAdd(&g_sumsq[s][c], sq);
}

__global__ void bn_finalize_kernel(const float* __restrict__ gamma,
                                   const float* __restrict__ beta, int n, int s) {
    int c = threadIdx.x;
    float invN = 1.0f / (float)n;
    float mu  = g_sum[s][c] * invN;
    float var = g_sumsq[s][c] * invN - mu * mu;
    float sc  = rsqrtf(var + EPS) * gamma[c];
    g_scale[s][c] = sc;
    g_shift[s][c] = beta[c] - mu * sc;
}

__global__ void bn_apply_kernel(int which, float* __restrict__ out,
                                int n4, int s, int relu) {
    const float* __restrict__ in = which ? g_y2 : g_y1;
    int i = blockIdx.x * blockDim.x + threadIdx.x;
    if (i >= n4) return;
    int c = (i << 2) & (HID - 1);
    float4 v  = ((const float4*)in)[i];
    float4 sc = *(const float4*)&g_scale[s][c];
    float4 sh = *(const float4*)&g_shift[s][c];
    v.x = v.x * sc.x + sh.x;
    v.y = v.y * sc.y + sh.y;
    v.z = v.z * sc.z + sh.z;
    v.w = v.w * sc.w + sh.w;
    if (relu) {
        v.x = fmaxf(v.x, 0.f);
        v.y = fmaxf(v.y, 0.f);
        v.z = fmaxf(v.z, 0.f);
        v.w = fmaxf(v.w, 0.f);
    }
    ((float4*)out)[i] = v;
}

// ================= CSR build =================
__global__ void count_kernel(const int* __restrict__ ei, int E_) {
    int e = blockIdx.x * blockDim.x + threadIdx.x;
    if (e < E_) atomicAdd(&g_cnt[ei[E_ + e]], 1);
}

__global__ void scan1_kernel(int n) {
    __shared__ int s[1024];
    int i = blockIdx.x * 1024 + threadIdx.x;
    int v = (i < n) ? g_cnt[i] : 0;
    s[threadIdx.x] = v;
    __syncthreads();
#pragma unroll
    for (int off = 1; off < 1024; off <<= 1) {
        int t = (threadIdx.x >= off) ? s[threadIdx.x - off] : 0;
        __syncthreads();
        s[threadIdx.x] += t;
        __syncthreads();
    }
    if (i < n) g_rowstart[i] = s[threadIdx.x] - v;
    if (threadIdx.x == 1023) g_bsum[blockIdx.x] = s[1023];
}

__global__ void scan2_kernel(int nb, int n) {
    if (threadIdx.x == 0) {
        int acc = 0;
        for (int b = 0; b < nb; b++) {
            int t = g_bsum[b];
            g_bsum[b] = acc;
            acc += t;
        }
        g_rowstart[n] = acc;
    }
}

__global__ void scan3_kernel(int n) {
    int i = blockIdx.x * blockDim.x + threadIdx.x;
    if (i < n) g_rowstart[i] += g_bsum[i >> 10];
}

__global__ void fill_kernel(const int* __restrict__ ei, int E_) {
    int e = blockIdx.x * blockDim.x + threadIdx.x;
    if (e >= E_) return;
    int dst = ei[E_ + e];
    int pos = atomicAdd(&g_fill[dst], 1);
    g_srcsorted[g_rowstart[dst] + pos] = ei[e];
}

// ================= aggregate: warp per dst node =================
__global__ __launch_bounds__(256) void aggregate_kernel(
        const float* __restrict__ feat, int n) {
    int w = (blockIdx.x * blockDim.x + threadIdx.x) >> 5;
    if (w >= n) return;
    int lane = threadIdx.x & 31;
    int beg = g_rowstart[w];
    int end = g_rowstart[w + 1];
    int c = lane << 2;

    float4 acc = make_float4(0.f, 0.f, 0.f, 0.f);
    int i = beg;
    for (; i + 4 <= end; i += 4) {
        int s0 = g_srcsorted[i];
        int s1 = g_srcsorted[i + 1];
        int s2 = g_srcsorted[i + 2];
        int s3 = g_srcsorted[i + 3];
        float4 v0 = *(const float4*)&feat[s0 * HID + c];
        float4 v1 = *(const float4*)&feat[s1 * HID + c];
        float4 v2 = *(const float4*)&feat[s2 * HID + c];
        float4 v3 = *(const float4*)&feat[s3 * HID + c];
        acc.x += v0.x + v1.x + v2.x + v3.x;
        acc.y += v0.y + v1.y + v2.y + v3.y;
        acc.z += v0.z + v1.z + v2.z + v3.z;
        acc.w += v0.w + v1.w + v2.w + v3.w;
    }
    for (; i < end; i++) {
        int s0 = g_srcsorted[i];
        float4 v0 = *(const float4*)&feat[s0 * HID + c];
        acc.x += v0.x;
        acc.y += v0.y;
        acc.z += v0.z;
        acc.w += v0.w;
    }
    float inv = 1.0f / fmaxf((float)(end - beg), 1.0f);
    acc.x *= inv;
    acc.y *= inv;
    acc.z *= inv;
    acc.w *= inv;
    *(float4*)&g_msg[w * HID + c] = acc;
}

// ================= launch =================
extern "C" void kernel_launch(void* const* d_in, const int* in_sizes, int n_in,
                              void* d_out, int out_size) {
    const float* x   = (const float*)d_in[0];
    const int*   ei  = (const int*)d_in[1];
    const float* W1  = (const float*)d_in[2];
    const float* b1  = (const float*)d_in[3];
    const float* g1  = (const float*)d_in[4];
    const float* be1 = (const float*)d_in[5];
    const float* Wl  = (const float*)d_in[6];
    const float* bl  = (const float*)d_in[7];
    const float* Wr  = (const float*)d_in[8];
    const float* g2  = (const float*)d_in[9];
    const float* be2 = (const float*)d_in[10];

    int n  = in_sizes[0] / D_IN;
    int E_ = in_sizes[1] / 2;

    float* feat = (float*)d_out;
    float* out2 = feat + (size_t)n * HID;

    int n4 = n * (HID / 4);
    int eblocks = (E_ + 255) / 256;
    int nblocks = (n + 255) / 256;
    int nb1024 = (n + 1023) / 1024;
    int tblocks = (n + 127) / 128;

    static int smem_set = 0;
    if (!smem_set) {
        cudaFuncSetAttribute(tc_gemm_kernel,
                             cudaFuncAttributeMaxDynamicSharedMemorySize, SM_GTOTAL);
        smem_set = 1;
    }

    // 0. weight tf32 images + zero accumulators
    wprep_kernel<<<(2 * 256 * 128 + 255) / 256, 256>>>(W1, Wl, Wr);
    zero_kernel<<<nblocks, 256>>>(n);
    // 1. linear1 (tf32 mma)
    tc_gemm_kernel<<<tblocks, 256, SM_GTOTAL>>>(0, x, b1, n);
    // 2-4. BN1 + ReLU -> feat
    bn_stats_kernel<<<nblocks, HID>>>(0, n, 0);
    bn_finalize_kernel<<<1, HID>>>(g1, be1, n, 0);
    bn_apply_kernel<<<(n4 + 255) / 256, 256>>>(0, feat, n4, 0, 1);
    // 5. CSR build
    count_kernel<<<eblocks, 256>>>(ei, E_);
    scan1_kernel<<<nb1024, 1024>>>(n);
    scan2_kernel<<<1, 32>>>(nb1024, n);
    scan3_kernel<<<nblocks, 256>>>(n);
    fill_kernel<<<eblocks, 256>>>(ei, E_);
    // 6. segmented mean aggregation
    aggregate_kernel<<<(n * 32 + 255) / 256, 256>>>(feat, n);
    // 7. SAGE linear (tf32 mma, fused lin_l + lin_r)
    tc_gemm_kernel<<<tblocks, 256, SM_GTOTAL>>>(1, feat, bl, n);
    // 8-10. BN2 -> out_feat
    bn_stats_kernel<<<nblocks, HID>>>(1, n, 1);
    bn_finalize_kernel<<<1, HID>>>(g2, be2, n, 1);
    bn_apply_kernel<<<(n4 + 255) / 256, 256>>>(1, out2, n4, 1, 0);
}

// round 9
// speedup vs baseline: 2.7114x; 1.0706x over previous
#include <cuda_runtime.h>
#include <cstdint>

// CustomStellarEncoder: Linear+BN+ReLU -> SAGEConv(mean) -> BN
// R9: BN column statistics fused into the tf32 GEMM epilogues (register ->
//     shfl -> smem -> global atomic). bn_stats kernels deleted (-69us).
//     tf32 3-split GEMM, CSR + warp aggregate unchanged from R8 (585us).

#define D_IN 256
#define HID 128
#define EPS 1e-5f
#define N_MAX 100000
#define E_MAX 3200000

// ================= scratch =================
__device__ float g_y1[(size_t)N_MAX * HID];
__device__ float g_msg[(size_t)N_MAX * HID];
__device__ float g_y2[(size_t)N_MAX * HID];
__device__ int   g_cnt[N_MAX];
__device__ int   g_fill[N_MAX];
__device__ int   g_rowstart[N_MAX + 1];
__device__ int   g_srcsorted[E_MAX];
__device__ int   g_bsum[128];
__device__ float g_sum[2][HID];
__device__ float g_sumsq[2][HID];
__device__ float g_scale[2][HID];
__device__ float g_shift[2][HID];
// weight tf32 hi/lo images: [K=256][132] float2 (hi, lo), row stride 132
__device__ float2 g_w1b[256 * 132];
__device__ float2 g_w2b[256 * 132];

// ================= tf32 helpers =================
__device__ __forceinline__ uint32_t f2tf(float x) {
    uint32_t r;
    asm("cvt.rna.tf32.f32 %0, %1;" : "=r"(r) : "f"(x));
    return r;
}

__device__ __forceinline__ void mma_tf32(float* d, uint32_t a0, uint32_t a1,
                                         uint32_t a2, uint32_t a3,
                                         uint32_t b0, uint32_t b1) {
    asm volatile(
        "mma.sync.aligned.m16n8k8.row.col.f32.tf32.tf32.f32 "
        "{%0,%1,%2,%3}, {%4,%5,%6,%7}, {%8,%9}, {%0,%1,%2,%3};"
        : "+f"(d[0]), "+f"(d[1]), "+f"(d[2]), "+f"(d[3])
        : "r"(a0), "r"(a1), "r"(a2), "r"(a3), "r"(b0), "r"(b1));
}

// ================= weight image prep (tf32 hi/lo split) =================
__global__ void wprep_kernel(const float* __restrict__ W1,
                             const float* __restrict__ Wl,
                             const float* __restrict__ Wr) {
    int idx = blockIdx.x * blockDim.x + threadIdx.x;
    if (idx >= 2 * 256 * 128) return;
    int wset = idx >> 15;
    int rem  = idx & 32767;
    int k = rem >> 7;
    int nn = rem & 127;
    float v;
    if (wset == 0) v = W1[k * 128 + nn];
    else           v = (k < 128) ? Wl[k * 128 + nn] : Wr[(k - 128) * 128 + nn];
    uint32_t hi = f2tf(v);
    float hif = __uint_as_float(hi);
    uint32_t lo = f2tf(v - hif);
    float2 hl = make_float2(hif, __uint_as_float(lo));
    if (wset == 0) g_w1b[k * 132 + nn] = hl;
    else           g_w2b[k * 132 + nn] = hl;
}

// ================= tf32 GEMM + fused BN stats =================
// mode 0: A row = x[row, 0:256] (stride 256), W = g_w1b, out = g_y1, stats s=0
// mode 1: A row = [g_msg[row] | feat[row]],   W = g_w2b, out = g_y2, stats s=1
#define A_STRIDE 68
#define B_STRIDE 132
#define SM_B_OFF 34816                       // 128*68*4 bytes
#define SM_GTOTAL (SM_B_OFF + 64 * 132 * 8)  // + 67584 = 102400

__global__ __launch_bounds__(256, 2) void tc_gemm_kernel(
        int mode, const float* __restrict__ xptr,
        const float* __restrict__ bias, int n) {
    extern __shared__ char smem[];
    float*  As = (float*)smem;                 // [128][68]
    float2* Bs = (float2*)(smem + SM_B_OFF);   // [64][132]

    int tid = threadIdx.x;
    int lane = tid & 31;
    int wid = tid >> 5;
    int row0 = blockIdx.x * 128;
    int wrow = wid * 16;

    float d[16][4];
#pragma unroll
    for (int t = 0; t < 16; t++)
#pragma unroll
        for (int q = 0; q < 4; q++) d[t][q] = 0.f;

    const float2* wimg = mode ? g_w2b : g_w1b;

    for (int c = 0; c < 4; c++) {
        int k0 = c * 64;
        // ---- load A chunk [128 rows x 64 cols] ----
        {
            int r = tid >> 1;
            int cb = (tid & 1) * 32;
            int grow = row0 + r;
            const float* src;
            if (mode == 0) {
                src = xptr + (size_t)grow * 256 + k0;
            } else {
                src = (k0 < 128 ? g_msg + (size_t)grow * 128 + k0
                                : xptr + (size_t)grow * 128 + (k0 - 128));
            }
            bool valid = grow < n;
#pragma unroll
            for (int j = 0; j < 8; j++) {
                float4 v = valid ? *(const float4*)(src + cb + j * 4)
                                 : make_float4(0.f, 0.f, 0.f, 0.f);
                *(float4*)&As[r * A_STRIDE + cb + j * 4] = v;
            }
        }
        // ---- load B chunk [64 k-rows x 132 float2] ----
        {
            const float4* src = (const float4*)(wimg + k0 * 132);
            float4* dst = (float4*)Bs;
            for (int i = tid; i < 4224; i += 256) dst[i] = src[i];
        }
        __syncthreads();

        // ---- compute: 8 k-steps of 8 ----
#pragma unroll
        for (int k8 = 0; k8 < 8; k8++) {
            int ar = wrow + (lane >> 2);
            int ac = k8 * 8 + (lane & 3);
            float a0 = As[ar * A_STRIDE + ac];
            float a1 = As[(ar + 8) * A_STRIDE + ac];
            float a2 = As[ar * A_STRIDE + ac + 4];
            float a3 = As[(ar + 8) * A_STRIDE + ac + 4];
            uint32_t ah0 = f2tf(a0), ah1 = f2tf(a1), ah2 = f2tf(a2), ah3 = f2tf(a3);
            uint32_t al0 = f2tf(a0 - __uint_as_float(ah0));
            uint32_t al1 = f2tf(a1 - __uint_as_float(ah1));
            uint32_t al2 = f2tf(a2 - __uint_as_float(ah2));
            uint32_t al3 = f2tf(a3 - __uint_as_float(ah3));
            int bk = k8 * 8 + (lane & 3);
            int bn = lane >> 2;
#pragma unroll
            for (int nt = 0; nt < 16; nt++) {
                float2 b0 = Bs[bk * B_STRIDE + nt * 8 + bn];
                float2 b1 = Bs[(bk + 4) * B_STRIDE + nt * 8 + bn];
                uint32_t bh0 = __float_as_uint(b0.x);
                uint32_t bl0 = __float_as_uint(b0.y);
                uint32_t bh1 = __float_as_uint(b1.x);
                uint32_t bl1 = __float_as_uint(b1.y);
                mma_tf32(d[nt], ah0, ah1, ah2, ah3, bh0, bh1);
                mma_tf32(d[nt], al0, al1, al2, al3, bh0, bh1);
                mma_tf32(d[nt], ah0, ah1, ah2, ah3, bl0, bl1);
            }
        }
        __syncthreads();
    }

    // ---- epilogue: bias add, store, fused BN stats ----
    float* ssum = (float*)smem;          // [128]  (reuse As region)
    float* ssq  = ((float*)smem) + 128;  // [128]
    ((float*)smem)[tid] = 0.f;           // zero 256 stat floats
    __syncthreads();

    float* outp = mode ? g_y2 : g_y1;
    int r0 = row0 + wrow + (lane >> 2);
    int r1 = r0 + 8;
    bool v0 = r0 < n, v1 = r1 < n;
#pragma unroll
    for (int nt = 0; nt < 16; nt++) {
        int col = nt * 8 + 2 * (lane & 3);
        float bx = __ldg(&bias[col]);
        float by = __ldg(&bias[col + 1]);
        float e0 = d[nt][0] + bx, e1 = d[nt][1] + by;
        float e2 = d[nt][2] + bx, e3 = d[nt][3] + by;
        if (v0) *(float2*)&outp[(size_t)r0 * HID + col] = make_float2(e0, e1);
        if (v1) *(float2*)&outp[(size_t)r1 * HID + col] = make_float2(e2, e3);
        // masked stat contributions
        float u0 = v0 ? e0 : 0.f, u1 = v0 ? e1 : 0.f;
        float u2 = v1 ? e2 : 0.f, u3 = v1 ? e3 : 0.f;
        float s0 = u0 + u2;                 // col
        float s1 = u1 + u3;                 // col+1
        float q0 = u0 * u0 + u2 * u2;
        float q1 = u1 * u1 + u3 * u3;
        // reduce over the 8 row-groups in this warp (lanes differing in bits 2..4)
#pragma unroll
        for (int m = 4; m <= 16; m <<= 1) {
            s0 += __shfl_xor_sync(0xffffffffu, s0, m);
            s1 += __shfl_xor_sync(0xffffffffu, s1, m);
            q0 += __shfl_xor_sync(0xffffffffu, q0, m);
            q1 += __shfl_xor_sync(0xffffffffu, q1, m);
        }
        if (lane < 4) {
            atomicAdd(&ssum[col], s0);
            atomicAdd(&ssum[col + 1], s1);
            atomicAdd(&ssq[col], q0);
            atomicAdd(&ssq[col + 1], q1);
        }
    }
    __syncthreads();
    {
        int s = mode;
        if (tid < 128) atomicAdd(&g_sum[s][tid], ssum[tid]);
        else           atomicAdd(&g_sumsq[s][tid - 128], ssq[tid - 128]);
    }
}

// ================= zero accumulators =================
__global__ void zero_kernel(int n) {
    int i = blockIdx.x * blockDim.x + threadIdx.x;
    if (i < n) {
        g_cnt[i] = 0;
        g_fill[i] = 0;
    }
    if (i < 2 * HID) {
        (&g_sum[0][0])[i] = 0.f;
        (&g_sumsq[0][0])[i] = 0.f;
    }
}

// ================= BN finalize / apply =================
__global__ void bn_finalize_kernel(const float* __restrict__ gamma,
                                   const float* __restrict__ beta, int n, int s) {
    int c = threadIdx.x;
    float invN = 1.0f / (float)n;
    float mu  = g_sum[s][c] * invN;
    float var = g_sumsq[s][c] * invN - mu * mu;
    float sc  = rsqrtf(var + EPS) * gamma[c];
    g_scale[s][c] = sc;
    g_shift[s][c] = beta[c] - mu * sc;
}

__global__ void bn_apply_kernel(int which, float* __restrict__ out,
                                int n4, int s, int relu) {
    const float* __restrict__ in = which ? g_y2 : g_y1;
    int i = blockIdx.x * blockDim.x + threadIdx.x;
    if (i >= n4) return;
    int c = (i << 2) & (HID - 1);
    float4 v  = ((const float4*)in)[i];
    float4 sc = *(const float4*)&g_scale[s][c];
    float4 sh = *(const float4*)&g_shift[s][c];
    v.x = v.x * sc.x + sh.x;
    v.y = v.y * sc.y + sh.y;
    v.z = v.z * sc.z + sh.z;
    v.w = v.w * sc.w + sh.w;
    if (relu) {
        v.x = fmaxf(v.x, 0.f);
        v.y = fmaxf(v.y, 0.f);
        v.z = fmaxf(v.z, 0.f);
        v.w = fmaxf(v.w, 0.f);
    }
    ((float4*)out)[i] = v;
}

// ================= CSR build =================
__global__ void count_kernel(const int* __restrict__ ei, int E_) {
    int e = blockIdx.x * blockDim.x + threadIdx.x;
    if (e < E_) atomicAdd(&g_cnt[ei[E_ + e]], 1);
}

__global__ void scan1_kernel(int n) {
    __shared__ int s[1024];
    int i = blockIdx.x * 1024 + threadIdx.x;
    int v = (i < n) ? g_cnt[i] : 0;
    s[threadIdx.x] = v;
    __syncthreads();
#pragma unroll
    for (int off = 1; off < 1024; off <<= 1) {
        int t = (threadIdx.x >= off) ? s[threadIdx.x - off] : 0;
        __syncthreads();
        s[threadIdx.x] += t;
        __syncthreads();
    }
    if (i < n) g_rowstart[i] = s[threadIdx.x] - v;
    if (threadIdx.x == 1023) g_bsum[blockIdx.x] = s[1023];
}

__global__ void scan2_kernel(int nb, int n) {
    if (threadIdx.x == 0) {
        int acc = 0;
        for (int b = 0; b < nb; b++) {
            int t = g_bsum[b];
            g_bsum[b] = acc;
            acc += t;
        }
        g_rowstart[n] = acc;
    }
}

__global__ void scan3_kernel(int n) {
    int i = blockIdx.x * blockDim.x + threadIdx.x;
    if (i < n) g_rowstart[i] += g_bsum[i >> 10];
}

__global__ void fill_kernel(const int* __restrict__ ei, int E_) {
    int e = blockIdx.x * blockDim.x + threadIdx.x;
    if (e >= E_) return;
    int dst = ei[E_ + e];
    int pos = atomicAdd(&g_fill[dst], 1);
    g_srcsorted[g_rowstart[dst] + pos] = ei[e];
}

// ================= aggregate: warp per dst node =================
__global__ __launch_bounds__(256) void aggregate_kernel(
        const float* __restrict__ feat, int n) {
    int w = (blockIdx.x * blockDim.x + threadIdx.x) >> 5;
    if (w >= n) return;
    int lane = threadIdx.x & 31;
    int beg = g_rowstart[w];
    int end = g_rowstart[w + 1];
    int c = lane << 2;

    float4 acc = make_float4(0.f, 0.f, 0.f, 0.f);
    int i = beg;
    for (; i + 4 <= end; i += 4) {
        int s0 = g_srcsorted[i];
        int s1 = g_srcsorted[i + 1];
        int s2 = g_srcsorted[i + 2];
        int s3 = g_srcsorted[i + 3];
        float4 v0 = *(const float4*)&feat[s0 * HID + c];
        float4 v1 = *(const float4*)&feat[s1 * HID + c];
        float4 v2 = *(const float4*)&feat[s2 * HID + c];
        float4 v3 = *(const float4*)&feat[s3 * HID + c];
        acc.x += v0.x + v1.x + v2.x + v3.x;
        acc.y += v0.y + v1.y + v2.y + v3.y;
        acc.z += v0.z + v1.z + v2.z + v3.z;
        acc.w += v0.w + v1.w + v2.w + v3.w;
    }
    for (; i < end; i++) {
        int s0 = g_srcsorted[i];
        float4 v0 = *(const float4*)&feat[s0 * HID + c];
        acc.x += v0.x;
        acc.y += v0.y;
        acc.z += v0.z;
        acc.w += v0.w;
    }
    float inv = 1.0f / fmaxf((float)(end - beg), 1.0f);
    acc.x *= inv;
    acc.y *= inv;
    acc.z *= inv;
    acc.w *= inv;
    *(float4*)&g_msg[w * HID + c] = acc;
}

// ================= launch =================
extern "C" void kernel_launch(void* const* d_in, const int* in_sizes, int n_in,
                              void* d_out, int out_size) {
    const float* x   = (const float*)d_in[0];
    const int*   ei  = (const int*)d_in[1];
    const float* W1  = (const float*)d_in[2];
    const float* b1  = (const float*)d_in[3];
    const float* g1  = (const float*)d_in[4];
    const float* be1 = (const float*)d_in[5];
    const float* Wl  = (const float*)d_in[6];
    const float* bl  = (const float*)d_in[7];
    const float* Wr  = (const float*)d_in[8];
    const float* g2  = (const float*)d_in[9];
    const float* be2 = (const float*)d_in[10];

    int n  = in_sizes[0] / D_IN;
    int E_ = in_sizes[1] / 2;

    float* feat = (float*)d_out;
    float* out2 = feat + (size_t)n * HID;

    int n4 = n * (HID / 4);
    int eblocks = (E_ + 255) / 256;
    int nblocks = (n + 255) / 256;
    int nb1024 = (n + 1023) / 1024;
    int tblocks = (n + 127) / 128;

    static int smem_set = 0;
    if (!smem_set) {
        cudaFuncSetAttribute(tc_gemm_kernel,
                             cudaFuncAttributeMaxDynamicSharedMemorySize, SM_GTOTAL);
        smem_set = 1;
    }

    // 0. weight tf32 images + zero accumulators
    wprep_kernel<<<(2 * 256 * 128 + 255) / 256, 256>>>(W1, Wl, Wr);
    zero_kernel<<<nblocks, 256>>>(n);
    // 1. linear1 (tf32 mma, fused BN1 stats)
    tc_gemm_kernel<<<tblocks, 256, SM_GTOTAL>>>(0, x, b1, n);
    // 2-3. BN1 finalize + apply(+ReLU) -> feat
    bn_finalize_kernel<<<1, HID>>>(g1, be1, n, 0);
    bn_apply_kernel<<<(n4 + 255) / 256, 256>>>(0, feat, n4, 0, 1);
    // 4. CSR build
    count_kernel<<<eblocks, 256>>>(ei, E_);
    scan1_kernel<<<nb1024, 1024>>>(n);
    scan2_kernel<<<1, 32>>>(nb1024, n);
    scan3_kernel<<<nblocks, 256>>>(n);
    fill_kernel<<<eblocks, 256>>>(ei, E_);
    // 5. segmented mean aggregation
    aggregate_kernel<<<(n * 32 + 255) / 256, 256>>>(feat, n);
    // 6. SAGE linear (tf32 mma, fused lin_l + lin_r, fused BN2 stats)
    tc_gemm_kernel<<<tblocks, 256, SM_GTOTAL>>>(1, feat, bl, n);
    // 7-8. BN2 finalize + apply -> out_feat
    bn_finalize_kernel<<<1, HID>>>(g2, be2, n, 1);
    bn_apply_kernel<<<(n4 + 255) / 256, 256>>>(1, out2, n4, 1, 0);
}

// round 15
// speedup vs baseline: 2.7214x; 1.0037x over previous
#include <cuda_runtime.h>
#include <cuda_fp16.h>
#include <cstdint>

// CustomStellarEncoder: Linear+BN+ReLU -> SAGEConv(mean) -> BN
// R10 (3rd submit; two prior broker-level container failures, source
//      unchanged): fp16 mirror of feat for the aggregate gather (halves L2
//      gather traffic) + GEMM2 feat chunks read fp16. Launch order shuffled
//      so tc_gemm mode0 is the profiled (4th) launch.
//      tf32 3-split GEMM + fused BN stats unchanged from R9 (546.9us).

#define D_IN 256
#define HID 128
#define EPS 1e-5f
#define N_MAX 100000
#define E_MAX 3200000

// ================= scratch =================
__device__ float g_y1[(size_t)N_MAX * HID];
__device__ float g_msg[(size_t)N_MAX * HID];
__device__ float g_y2[(size_t)N_MAX * HID];
__device__ __half2 g_feat16[(size_t)N_MAX * 64];   // fp16 mirror of feat
__device__ int   g_cnt[N_MAX];
__device__ int   g_fill[N_MAX];
__device__ int   g_rowstart[N_MAX + 1];
__device__ int   g_srcsorted[E_MAX];
__device__ int   g_bsum[128];
__device__ float g_sum[2][HID];
__device__ float g_sumsq[2][HID];
__device__ float g_scale[2][HID];
__device__ float g_shift[2][HID];
// weight tf32 hi/lo images: [K=256][132] float2 (hi, lo), row stride 132
__device__ float2 g_w1b[256 * 132];
__device__ float2 g_w2b[256 * 132];

// ================= tf32 helpers =================
__device__ __forceinline__ uint32_t f2tf(float x) {
    uint32_t r;
    asm("cvt.rna.tf32.f32 %0, %1;" : "=r"(r) : "f"(x));
    return r;
}

__device__ __forceinline__ void mma_tf32(float* d, uint32_t a0, uint32_t a1,
                                         uint32_t a2, uint32_t a3,
                                         uint32_t b0, uint32_t b1) {
    asm volatile(
        "mma.sync.aligned.m16n8k8.row.col.f32.tf32.tf32.f32 "
        "{%0,%1,%2,%3}, {%4,%5,%6,%7}, {%8,%9}, {%0,%1,%2,%3};"
        : "+f"(d[0]), "+f"(d[1]), "+f"(d[2]), "+f"(d[3])
        : "r"(a0), "r"(a1), "r"(a2), "r"(a3), "r"(b0), "r"(b1));
}

// ================= weight image prep (tf32 hi/lo split) =================
__global__ void wprep_kernel(const float* __restrict__ W1,
                             const float* __restrict__ Wl,
                             const float* __restrict__ Wr) {
    int idx = blockIdx.x * blockDim.x + threadIdx.x;
    if (idx >= 2 * 256 * 128) return;
    int wset = idx >> 15;
    int rem  = idx & 32767;
    int k = rem >> 7;
    int nn = rem & 127;
    float v;
    if (wset == 0) v = W1[k * 128 + nn];
    else           v = (k < 128) ? Wl[k * 128 + nn] : Wr[(k - 128) * 128 + nn];
    uint32_t hi = f2tf(v);
    float hif = __uint_as_float(hi);
    uint32_t lo = f2tf(v - hif);
    float2 hl = make_float2(hif, __uint_as_float(lo));
    if (wset == 0) g_w1b[k * 132 + nn] = hl;
    else           g_w2b[k * 132 + nn] = hl;
}

// ================= tf32 GEMM + fused BN stats =================
// mode 0: A row = x[row, 0:256] (stride 256), W = g_w1b, out = g_y1, stats s=0
// mode 1: A row = [g_msg[row] | feat16[row]], W = g_w2b, out = g_y2, stats s=1
#define A_STRIDE 68
#define B_STRIDE 132
#define SM_B_OFF 34816                       // 128*68*4 bytes
#define SM_GTOTAL (SM_B_OFF + 64 * 132 * 8)  // + 67584 = 102400

__global__ __launch_bounds__(256, 2) void tc_gemm_kernel(
        int mode, const float* __restrict__ xptr,
        const float* __restrict__ bias, int n) {
    extern __shared__ char smem[];
    float*  As = (float*)smem;                 // [128][68]
    float2* Bs = (float2*)(smem + SM_B_OFF);   // [64][132]

    int tid = threadIdx.x;
    int lane = tid & 31;
    int wid = tid >> 5;
    int row0 = blockIdx.x * 128;
    int wrow = wid * 16;

    float d[16][4];
#pragma unroll
    for (int t = 0; t < 16; t++)
#pragma unroll
        for (int q = 0; q < 4; q++) d[t][q] = 0.f;

    const float2* wimg = mode ? g_w2b : g_w1b;

    for (int c = 0; c < 4; c++) {
        int k0 = c * 64;
        // ---- load A chunk [128 rows x 64 cols] ----
        {
            int r = tid >> 1;
            int cb = (tid & 1) * 32;
            int grow = row0 + r;
            bool valid = grow < n;
            if (mode == 1 && k0 >= 128) {
                // feat chunk from fp16 mirror
                const __half2* src = g_feat16 + (size_t)grow * 64 + ((k0 - 128) >> 1) + (cb >> 1);
#pragma unroll
                for (int j = 0; j < 8; j++) {
                    float4 v;
                    if (valid) {
                        uint2 raw = *(const uint2*)(src + j * 2);
                        __half2 h0 = *(__half2*)&raw.x;
                        __half2 h1 = *(__half2*)&raw.y;
                        float2 f0 = __half22float2(h0);
                        float2 f1 = __half22float2(h1);
                        v = make_float4(f0.x, f0.y, f1.x, f1.y);
                    } else {
                        v = make_float4(0.f, 0.f, 0.f, 0.f);
                    }
                    *(float4*)&As[r * A_STRIDE + cb + j * 4] = v;
                }
            } else {
                const float* src;
                if (mode == 0) src = xptr + (size_t)grow * 256 + k0;
                else           src = g_msg + (size_t)grow * 128 + k0;
#pragma unroll
                for (int j = 0; j < 8; j++) {
                    float4 v = valid ? *(const float4*)(src + cb + j * 4)
                                     : make_float4(0.f, 0.f, 0.f, 0.f);
                    *(float4*)&As[r * A_STRIDE + cb + j * 4] = v;
                }
            }
        }
        // ---- load B chunk [64 k-rows x 132 float2] ----
        {
            const float4* src = (const float4*)(wimg + k0 * 132);
            float4* dst = (float4*)Bs;
            for (int i = tid; i < 4224; i += 256) dst[i] = src[i];
        }
        __syncthreads();

        // ---- compute: 8 k-steps of 8 ----
#pragma unroll
        for (int k8 = 0; k8 < 8; k8++) {
            int ar = wrow + (lane >> 2);
            int ac = k8 * 8 + (lane & 3);
            float a0 = As[ar * A_STRIDE + ac];
            float a1 = As[(ar + 8) * A_STRIDE + ac];
            float a2 = As[ar * A_STRIDE + ac + 4];
            float a3 = As[(ar + 8) * A_STRIDE + ac + 4];
            uint32_t ah0 = f2tf(a0), ah1 = f2tf(a1), ah2 = f2tf(a2), ah3 = f2tf(a3);
            uint32_t al0 = f2tf(a0 - __uint_as_float(ah0));
            uint32_t al1 = f2tf(a1 - __uint_as_float(ah1));
            uint32_t al2 = f2tf(a2 - __uint_as_float(ah2));
            uint32_t al3 = f2tf(a3 - __uint_as_float(ah3));
            int bk = k8 * 8 + (lane & 3);
            int bn = lane >> 2;
#pragma unroll
            for (int nt = 0; nt < 16; nt++) {
                float2 b0 = Bs[bk * B_STRIDE + nt * 8 + bn];
                float2 b1 = Bs[(bk + 4) * B_STRIDE + nt * 8 + bn];
                uint32_t bh0 = __float_as_uint(b0.x);
                uint32_t bl0 = __float_as_uint(b0.y);
                uint32_t bh1 = __float_as_uint(b1.x);
                uint32_t bl1 = __float_as_uint(b1.y);
                mma_tf32(d[nt], ah0, ah1, ah2, ah3, bh0, bh1);
                mma_tf32(d[nt], al0, al1, al2, al3, bh0, bh1);
                mma_tf32(d[nt], ah0, ah1, ah2, ah3, bl0, bl1);
            }
        }
        __syncthreads();
    }

    // ---- epilogue: bias add, store, fused BN stats ----
    float* ssum = (float*)smem;
    float* ssq  = ((float*)smem) + 128;
    ((float*)smem)[tid] = 0.f;
    __syncthreads();

    float* outp = mode ? g_y2 : g_y1;
    int r0 = row0 + wrow + (lane >> 2);
    int r1 = r0 + 8;
    bool v0 = r0 < n, v1 = r1 < n;
#pragma unroll
    for (int nt = 0; nt < 16; nt++) {
        int col = nt * 8 + 2 * (lane & 3);
        float bx = __ldg(&bias[col]);
        float by = __ldg(&bias[col + 1]);
        float e0 = d[nt][0] + bx, e1 = d[nt][1] + by;
        float e2 = d[nt][2] + bx, e3 = d[nt][3] + by;
        if (v0) *(float2*)&outp[(size_t)r0 * HID + col] = make_float2(e0, e1);
        if (v1) *(float2*)&outp[(size_t)r1 * HID + col] = make_float2(e2, e3);
        float u0 = v0 ? e0 : 0.f, u1 = v0 ? e1 : 0.f;
        float u2 = v1 ? e2 : 0.f, u3 = v1 ? e3 : 0.f;
        float s0 = u0 + u2;
        float s1 = u1 + u3;
        float q0 = u0 * u0 + u2 * u2;
        float q1 = u1 * u1 + u3 * u3;
#pragma unroll
        for (int m = 4; m <= 16; m <<= 1) {
            s0 += __shfl_xor_sync(0xffffffffu, s0, m);
            s1 += __shfl_xor_sync(0xffffffffu, s1, m);
            q0 += __shfl_xor_sync(0xffffffffu, q0, m);
            q1 += __shfl_xor_sync(0xffffffffu, q1, m);
        }
        if (lane < 4) {
            atomicAdd(&ssum[col], s0);
            atomicAdd(&ssum[col + 1], s1);
            atomicAdd(&ssq[col], q0);
            atomicAdd(&ssq[col + 1], q1);
        }
    }
    __syncthreads();
    {
        int s = mode;
        if (tid < 128) atomicAdd(&g_sum[s][tid], ssum[tid]);
        else           atomicAdd(&g_sumsq[s][tid - 128], ssq[tid - 128]);
    }
}

// ================= zero accumulators =================
__global__ void zero_kernel(int n) {
    int i = blockIdx.x * blockDim.x + threadIdx.x;
    if (i < n) {
        g_cnt[i] = 0;
        g_fill[i] = 0;
    }
    if (i < 2 * HID) {
        (&g_sum[0][0])[i] = 0.f;
        (&g_sumsq[0][0])[i] = 0.f;
    }
}

// ================= BN finalize / apply =================
__global__ void bn_finalize_kernel(const float* __restrict__ gamma,
                                   const float* __restrict__ beta, int n, int s) {
    int c = threadIdx.x;
    float invN = 1.0f / (float)n;
    float mu  = g_sum[s][c] * invN;
    float var = g_sumsq[s][c] * invN - mu * mu;
    float sc  = rsqrtf(var + EPS) * gamma[c];
    g_scale[s][c] = sc;
    g_shift[s][c] = beta[c] - mu * sc;
}

// which==0: also emit fp16 mirror (feat path, relu=1)
__global__ void bn_apply_kernel(int which, float* __restrict__ out,
                                int n4, int s, int relu) {
    const float* __restrict__ in = which ? g_y2 : g_y1;
    int i = blockIdx.x * blockDim.x + threadIdx.x;
    if (i >= n4) return;
    int c = (i << 2) & (HID - 1);
    float4 v  = ((const float4*)in)[i];
    float4 sc = *(const float4*)&g_scale[s][c];
    float4 sh = *(const float4*)&g_shift[s][c];
    v.x = v.x * sc.x + sh.x;
    v.y = v.y * sc.y + sh.y;
    v.z = v.z * sc.z + sh.z;
    v.w = v.w * sc.w + sh.w;
    if (relu) {
        v.x = fmaxf(v.x, 0.f);
        v.y = fmaxf(v.y, 0.f);
        v.z = fmaxf(v.z, 0.f);
        v.w = fmaxf(v.w, 0.f);
    }
    ((float4*)out)[i] = v;
    if (which == 0) {
        __half2 h0 = __floats2half2_rn(v.x, v.y);
        __half2 h1 = __floats2half2_rn(v.z, v.w);
        uint2 packed;
        packed.x = *(uint32_t*)&h0;
        packed.y = *(uint32_t*)&h1;
        *(uint2*)&g_feat16[(size_t)i * 2] = packed;
    }
}

// ================= CSR build =================
__global__ void count_kernel(const int* __restrict__ ei, int E_) {
    int e = blockIdx.x * blockDim.x + threadIdx.x;
    if (e < E_) atomicAdd(&g_cnt[ei[E_ + e]], 1);
}

__global__ void scan1_kernel(int n) {
    __shared__ int s[1024];
    int i = blockIdx.x * 1024 + threadIdx.x;
    int v = (i < n) ? g_cnt[i] : 0;
    s[threadIdx.x] = v;
    __syncthreads();
#pragma unroll
    for (int off = 1; off < 1024; off <<= 1) {
        int t = (threadIdx.x >= off) ? s[threadIdx.x - off] : 0;
        __syncthreads();
        s[threadIdx.x] += t;
        __syncthreads();
    }
    if (i < n) g_rowstart[i] = s[threadIdx.x] - v;
    if (threadIdx.x == 1023) g_bsum[blockIdx.x] = s[1023];
}

__global__ void scan2_kernel(int nb, int n) {
    if (threadIdx.x == 0) {
        int acc = 0;
        for (int b = 0; b < nb; b++) {
            int t = g_bsum[b];
            g_bsum[b] = acc;
            acc += t;
        }
        g_rowstart[n] = acc;
    }
}

__global__ void scan3_kernel(int n) {
    int i = blockIdx.x * blockDim.x + threadIdx.x;
    if (i < n) g_rowstart[i] += g_bsum[i >> 10];
}

__global__ void fill_kernel(const int* __restrict__ ei, int E_) {
    int e = blockIdx.x * blockDim.x + threadIdx.x;
    if (e >= E_) return;
    int dst = ei[E_ + e];
    int pos = atomicAdd(&g_fill[dst], 1);
    g_srcsorted[g_rowstart[dst] + pos] = ei[e];
}

// ================= aggregate: warp per dst node, fp16 gather =================
__global__ __launch_bounds__(256) void aggregate_kernel(int n) {
    int w = (blockIdx.x * blockDim.x + threadIdx.x) >> 5;
    if (w >= n) return;
    int lane = threadIdx.x & 31;
    int beg = g_rowstart[w];
    int end = g_rowstart[w + 1];

    float4 acc = make_float4(0.f, 0.f, 0.f, 0.f);
    int i = beg;
    for (; i + 4 <= end; i += 4) {
        int s0 = g_srcsorted[i];
        int s1 = g_srcsorted[i + 1];
        int s2 = g_srcsorted[i + 2];
        int s3 = g_srcsorted[i + 3];
        uint2 r0 = *(const uint2*)&g_feat16[(size_t)s0 * 64 + lane * 2];
        uint2 r1 = *(const uint2*)&g_feat16[(size_t)s1 * 64 + lane * 2];
        uint2 r2 = *(const uint2*)&g_feat16[(size_t)s2 * 64 + lane * 2];
        uint2 r3 = *(const uint2*)&g_feat16[(size_t)s3 * 64 + lane * 2];
        float2 a0 = __half22float2(*(__half2*)&r0.x), b0 = __half22float2(*(__half2*)&r0.y);
        float2 a1 = __half22float2(*(__half2*)&r1.x), b1 = __half22float2(*(__half2*)&r1.y);
        float2 a2 = __half22float2(*(__half2*)&r2.x), b2 = __half22float2(*(__half2*)&r2.y);
        float2 a3 = __half22float2(*(__half2*)&r3.x), b3 = __half22float2(*(__half2*)&r3.y);
        acc.x += (a0.x + a1.x) + (a2.x + a3.x);
        acc.y += (a0.y + a1.y) + (a2.y + a3.y);
        acc.z += (b0.x + b1.x) + (b2.x + b3.x);
        acc.w += (b0.y + b1.y) + (b2.y + b3.y);
    }
    for (; i < end; i++) {
        int s0 = g_srcsorted[i];
        uint2 r0 = *(const uint2*)&g_feat16[(size_t)s0 * 64 + lane * 2];
        float2 a0 = __half22float2(*(__half2*)&r0.x), b0 = __half22float2(*(__half2*)&r0.y);
        acc.x += a0.x;
        acc.y += a0.y;
        acc.z += b0.x;
        acc.w += b0.y;
    }
    float inv = 1.0f / fmaxf((float)(end - beg), 1.0f);
    acc.x *= inv;
    acc.y *= inv;
    acc.z *= inv;
    acc.w *= inv;
    *(float4*)&g_msg[w * HID + lane * 4] = acc;
}

// ================= launch =================
extern "C" void kernel_launch(void* const* d_in, const int* in_sizes, int n_in,
                              void* d_out, int out_size) {
    const float* x   = (const float*)d_in[0];
    const int*   ei  = (const int*)d_in[1];
    const float* W1  = (const float*)d_in[2];
    const float* b1  = (const float*)d_in[3];
    const float* g1  = (const float*)d_in[4];
    const float* be1 = (const float*)d_in[5];
    const float* Wl  = (const float*)d_in[6];
    const float* bl  = (const float*)d_in[7];
    const float* Wr  = (const float*)d_in[8];
    const float* g2  = (const float*)d_in[9];
    const float* be2 = (const float*)d_in[10];

    int n  = in_sizes[0] / D_IN;
    int E_ = in_sizes[1] / 2;

    float* feat = (float*)d_out;
    float* out2 = feat + (size_t)n * HID;

    int n4 = n * (HID / 4);
    int eblocks = (E_ + 255) / 256;
    int nblocks = (n + 255) / 256;
    int nb1024 = (n + 1023) / 1024;
    int tblocks = (n + 127) / 128;

    static int smem_set = 0;
    if (!smem_set) {
        cudaFuncSetAttribute(tc_gemm_kernel,
                             cudaFuncAttributeMaxDynamicSharedMemorySize, SM_GTOTAL);
        smem_set = 1;
    }

    // launch order arranged so tc_gemm mode0 is launch index 3 (profiled slot)
    zero_kernel<<<nblocks, 256>>>(n);                                  // 0
    wprep_kernel<<<(2 * 256 * 128 + 255) / 256, 256>>>(W1, Wl, Wr);    // 1
    count_kernel<<<eblocks, 256>>>(ei, E_);                            // 2
    tc_gemm_kernel<<<tblocks, 256, SM_GTOTAL>>>(0, x, b1, n);          // 3 (profiled)
    bn_finalize_kernel<<<1, HID>>>(g1, be1, n, 0);                     // 4
    bn_apply_kernel<<<(n4 + 255) / 256, 256>>>(0, feat, n4, 0, 1);     // 5
    scan1_kernel<<<nb1024, 1024>>>(n);
    scan2_kernel<<<1, 32>>>(nb1024, n);
    scan3_kernel<<<nblocks, 256>>>(n);
    fill_kernel<<<eblocks, 256>>>(ei, E_);
    aggregate_kernel<<<(n * 32 + 255) / 256, 256>>>(n);
    tc_gemm_kernel<<<tblocks, 256, SM_GTOTAL>>>(1, nullptr, bl, n);
    bn_finalize_kernel<<<1, HID>>>(g2, be2, n, 1);
    bn_apply_kernel<<<(n4 + 255) / 256, 256>>>(1, out2, n4, 1, 0);
}

// round 16
// speedup vs baseline: 3.5978x; 1.3220x over previous
#include <cuda_runtime.h>
#include <cuda_fp16.h>
#include <cuda_bf16.h>
#include <cstdint>

// CustomStellarEncoder: Linear+BN+ReLU -> SAGEConv(mean) -> BN
// R16: GEMM core switched tf32 m16n8k8 -> bf16 m16n8k16 (3-term hi/lo
//      split, pre-split operands packed {hi,lo} in uint2 -> one LDS.64
//      feeds all 3 MMA terms). Halves HMMA + LDS instruction counts.
//      fp16 aggregate + fused BN stats + CSR unchanged from R15 (544.9us).

#define D_IN 256
#define HID 128
#define EPS 1e-5f
#define N_MAX 100000
#define E_MAX 3200000

// ================= scratch =================
__device__ float g_y1[(size_t)N_MAX * HID];
__device__ float g_msg[(size_t)N_MAX * HID];
__device__ float g_y2[(size_t)N_MAX * HID];
__device__ __half2 g_feat16[(size_t)N_MAX * 64];   // fp16 mirror of feat
__device__ int   g_cnt[N_MAX];
__device__ int   g_fill[N_MAX];
__device__ int   g_rowstart[N_MAX + 1];
__device__ int   g_srcsorted[E_MAX];
__device__ int   g_bsum[128];
__device__ float g_sum[2][HID];
__device__ float g_sumsq[2][HID];
__device__ float g_scale[2][HID];
__device__ float g_shift[2][HID];
// weight bf16 hi/lo images: [kq=K/2][132 n] x uint16[4] = {hi0,hi1,lo0,lo1}
__device__ uint16_t g_w1c[128 * 132 * 4];
__device__ uint16_t g_w2c[128 * 132 * 4];

// ================= bf16 split helpers =================
__device__ __forceinline__ void split_pair(float f0, float f1,
                                           uint32_t& hi, uint32_t& lo) {
    __nv_bfloat16 h0 = __float2bfloat16(f0);
    __nv_bfloat16 h1 = __float2bfloat16(f1);
    __nv_bfloat16 l0 = __float2bfloat16(f0 - __bfloat162float(h0));
    __nv_bfloat16 l1 = __float2bfloat16(f1 - __bfloat162float(h1));
    hi = (uint32_t)(*(uint16_t*)&h0) | ((uint32_t)(*(uint16_t*)&h1) << 16);
    lo = (uint32_t)(*(uint16_t*)&l0) | ((uint32_t)(*(uint16_t*)&l1) << 16);
}

__device__ __forceinline__ void mma_bf16(float* d, uint32_t a0, uint32_t a1,
                                         uint32_t a2, uint32_t a3,
                                         uint32_t b0, uint32_t b1) {
    asm volatile(
        "mma.sync.aligned.m16n8k16.row.col.f32.bf16.bf16.f32 "
        "{%0,%1,%2,%3}, {%4,%5,%6,%7}, {%8,%9}, {%0,%1,%2,%3};"
        : "+f"(d[0]), "+f"(d[1]), "+f"(d[2]), "+f"(d[3])
        : "r"(a0), "r"(a1), "r"(a2), "r"(a3), "r"(b0), "r"(b1));
}

// ================= weight image prep (bf16 hi/lo split) =================
// wset 0: W1 [256x128]; wset 1: rows 0-127 = Wl, rows 128-255 = Wr
__global__ void wprep_kernel(const float* __restrict__ W1,
                             const float* __restrict__ Wl,
                             const float* __restrict__ Wr) {
    int idx = blockIdx.x * blockDim.x + threadIdx.x;
    if (idx >= 2 * 256 * 128) return;
    int wset = idx >> 15;
    int rem  = idx & 32767;
    int k = rem >> 7;
    int nn = rem & 127;
    float v;
    if (wset == 0) v = W1[k * 128 + nn];
    else           v = (k < 128) ? Wl[k * 128 + nn] : Wr[(k - 128) * 128 + nn];
    __nv_bfloat16 h = __float2bfloat16(v);
    __nv_bfloat16 l = __float2bfloat16(v - __bfloat162float(h));
    uint32_t base = (uint32_t)(((k >> 1) * 132 + nn) << 2);
    uint16_t* dst = wset ? g_w2c : g_w1c;
    dst[base + (k & 1)]     = *(uint16_t*)&h;
    dst[base + 2 + (k & 1)] = *(uint16_t*)&l;
}

// ================= bf16 GEMM + fused BN stats =================
// mode 0: A row = x[row, 0:256] (stride 256), W = g_w1c, out = g_y1, stats 0
// mode 1: A row = [g_msg fp32 | g_feat16 fp16], W = g_w2c, out = g_y2, stats 1
// smem: A [128 rows][36 uint2] = 36864 B ; B [32 kq][132 uint2] = 33792 B
#define A_STRIDE2 36
#define B_STRIDE2 132
#define SM_B_OFF2 36864
#define SM_GTOTAL (SM_B_OFF2 + 32 * 132 * 8)   // 70656

__global__ __launch_bounds__(256, 2) void tc_gemm_kernel(
        int mode, const float* __restrict__ xptr,
        const float* __restrict__ bias, int n) {
    extern __shared__ char smem[];
    uint2* As = (uint2*)smem;                   // [128][36]
    uint2* Bs = (uint2*)(smem + SM_B_OFF2);     // [32][132]

    int tid = threadIdx.x;
    int lane = tid & 31;
    int wid = tid >> 5;
    int row0 = blockIdx.x * 128;
    int wrow = wid * 16;

    float d[16][4];
#pragma unroll
    for (int t = 0; t < 16; t++)
#pragma unroll
        for (int q = 0; q < 4; q++) d[t][q] = 0.f;

    const uint16_t* wimg = mode ? g_w2c : g_w1c;

    for (int c = 0; c < 4; c++) {
        int k0 = c * 64;
        // ---- fill A chunk: 128 rows x 64 k as 32 {hi,lo} uint2 per row ----
        {
            int r = tid >> 1;
            int cb = (tid & 1) * 32;      // k offset within chunk
            int grow = row0 + r;
            bool valid = grow < n;
            float f[32];
            if (valid) {
                if (mode == 1 && k0 >= 128) {
                    const uint2* src = (const uint2*)(g_feat16 +
                        (size_t)grow * 64 + ((k0 - 128 + cb) >> 1));
#pragma unroll
                    for (int j = 0; j < 8; j++) {
                        uint2 raw = src[j];
                        float2 f0 = __half22float2(*(__half2*)&raw.x);
                        float2 f1 = __half22float2(*(__half2*)&raw.y);
                        f[j * 4 + 0] = f0.x; f[j * 4 + 1] = f0.y;
                        f[j * 4 + 2] = f1.x; f[j * 4 + 3] = f1.y;
                    }
                } else {
                    const float* src = (mode == 0)
                        ? xptr + (size_t)grow * 256 + k0 + cb
                        : g_msg + (size_t)grow * 128 + k0 + cb;
#pragma unroll
                    for (int j = 0; j < 8; j++) {
                        float4 v = *(const float4*)(src + j * 4);
                        f[j * 4 + 0] = v.x; f[j * 4 + 1] = v.y;
                        f[j * 4 + 2] = v.z; f[j * 4 + 3] = v.w;
                    }
                }
            } else {
#pragma unroll
                for (int q = 0; q < 32; q++) f[q] = 0.f;
            }
#pragma unroll
            for (int j = 0; j < 16; j++) {
                uint32_t hi, lo;
                split_pair(f[j * 2], f[j * 2 + 1], hi, lo);
                As[r * A_STRIDE2 + (cb >> 1) + j] = make_uint2(hi, lo);
            }
        }
        // ---- fill B chunk: copy 32 kq x 132 uint2 from precomputed image ----
        {
            const uint4* src = (const uint4*)(wimg + (size_t)(c * 32) * 132 * 4);
            uint4* dst = (uint4*)Bs;
            for (int i = tid; i < 2112; i += 256) dst[i] = src[i];
        }
        __syncthreads();

        // ---- compute: 4 k16-steps ----
#pragma unroll
        for (int t = 0; t < 4; t++) {
            int r = wrow + (lane >> 2);
            int kq = t * 8 + (lane & 3);
            uint2 A00 = As[r * A_STRIDE2 + kq];            // a0 {hi,lo}
            uint2 A10 = As[(r + 8) * A_STRIDE2 + kq];      // a1
            uint2 A01 = As[r * A_STRIDE2 + kq + 4];        // a2
            uint2 A11 = As[(r + 8) * A_STRIDE2 + kq + 4];  // a3
            int bn = lane >> 2;
#pragma unroll
            for (int nt = 0; nt < 16; nt++) {
                uint2 B0 = Bs[kq * B_STRIDE2 + nt * 8 + bn];
                uint2 B1 = Bs[(kq + 4) * B_STRIDE2 + nt * 8 + bn];
                mma_bf16(d[nt], A00.x, A10.x, A01.x, A11.x, B0.x, B1.x); // hi*hi
                mma_bf16(d[nt], A00.y, A10.y, A01.y, A11.y, B0.x, B1.x); // lo*hi
                mma_bf16(d[nt], A00.x, A10.x, A01.x, A11.x, B0.y, B1.y); // hi*lo
            }
        }
        __syncthreads();
    }

    // ---- epilogue: bias add, store, fused BN stats ----
    float* ssum = (float*)smem;
    float* ssq  = ((float*)smem) + 128;
    ((float*)smem)[tid] = 0.f;
    __syncthreads();

    float* outp = mode ? g_y2 : g_y1;
    int r0 = row0 + wrow + (lane >> 2);
    int r1 = r0 + 8;
    bool v0 = r0 < n, v1 = r1 < n;
#pragma unroll
    for (int nt = 0; nt < 16; nt++) {
        int col = nt * 8 + 2 * (lane & 3);
        float bx = __ldg(&bias[col]);
        float by = __ldg(&bias[col + 1]);
        float e0 = d[nt][0] + bx, e1 = d[nt][1] + by;
        float e2 = d[nt][2] + bx, e3 = d[nt][3] + by;
        if (v0) *(float2*)&outp[(size_t)r0 * HID + col] = make_float2(e0, e1);
        if (v1) *(float2*)&outp[(size_t)r1 * HID + col] = make_float2(e2, e3);
        float u0 = v0 ? e0 : 0.f, u1 = v0 ? e1 : 0.f;
        float u2 = v1 ? e2 : 0.f, u3 = v1 ? e3 : 0.f;
        float s0 = u0 + u2;
        float s1 = u1 + u3;
        float q0 = u0 * u0 + u2 * u2;
        float q1 = u1 * u1 + u3 * u3;
#pragma unroll
        for (int m = 4; m <= 16; m <<= 1) {
            s0 += __shfl_xor_sync(0xffffffffu, s0, m);
            s1 += __shfl_xor_sync(0xffffffffu, s1, m);
            q0 += __shfl_xor_sync(0xffffffffu, q0, m);
            q1 += __shfl_xor_sync(0xffffffffu, q1, m);
        }
        if (lane < 4) {
            atomicAdd(&ssum[col], s0);
            atomicAdd(&ssum[col + 1], s1);
            atomicAdd(&ssq[col], q0);
            atomicAdd(&ssq[col + 1], q1);
        }
    }
    __syncthreads();
    {
        int s = mode;
        if (tid < 128) atomicAdd(&g_sum[s][tid], ssum[tid]);
        else           atomicAdd(&g_sumsq[s][tid - 128], ssq[tid - 128]);
    }
}

// ================= zero accumulators =================
__global__ void zero_kernel(int n) {
    int i = blockIdx.x * blockDim.x + threadIdx.x;
    if (i < n) {
        g_cnt[i] = 0;
        g_fill[i] = 0;
    }
    if (i < 2 * HID) {
        (&g_sum[0][0])[i] = 0.f;
        (&g_sumsq[0][0])[i] = 0.f;
    }
}

// ================= BN finalize / apply =================
__global__ void bn_finalize_kernel(const float* __restrict__ gamma,
                                   const float* __restrict__ beta, int n, int s) {
    int c = threadIdx.x;
    float invN = 1.0f / (float)n;
    float mu  = g_sum[s][c] * invN;
    float var = g_sumsq[s][c] * invN - mu * mu;
    float sc  = rsqrtf(var + EPS) * gamma[c];
    g_scale[s][c] = sc;
    g_shift[s][c] = beta[c] - mu * sc;
}

// which==0: also emit fp16 mirror (feat path, relu=1)
__global__ void bn_apply_kernel(int which, float* __restrict__ out,
                                int n4, int s, int relu) {
    const float* __restrict__ in = which ? g_y2 : g_y1;
    int i = blockIdx.x * blockDim.x + threadIdx.x;
    if (i >= n4) return;
    int c = (i << 2) & (HID - 1);
    float4 v  = ((const float4*)in)[i];
    float4 sc = *(const float4*)&g_scale[s][c];
    float4 sh = *(const float4*)&g_shift[s][c];
    v.x = v.x * sc.x + sh.x;
    v.y = v.y * sc.y + sh.y;
    v.z = v.z * sc.z + sh.z;
    v.w = v.w * sc.w + sh.w;
    if (relu) {
        v.x = fmaxf(v.x, 0.f);
        v.y = fmaxf(v.y, 0.f);
        v.z = fmaxf(v.z, 0.f);
        v.w = fmaxf(v.w, 0.f);
    }
    ((float4*)out)[i] = v;
    if (which == 0) {
        __half2 h0 = __floats2half2_rn(v.x, v.y);
        __half2 h1 = __floats2half2_rn(v.z, v.w);
        uint2 packed;
        packed.x = *(uint32_t*)&h0;
        packed.y = *(uint32_t*)&h1;
        *(uint2*)&g_feat16[(size_t)i * 2] = packed;
    }
}

// ================= CSR build =================
__global__ void count_kernel(const int* __restrict__ ei, int E_) {
    int e = blockIdx.x * blockDim.x + threadIdx.x;
    if (e < E_) atomicAdd(&g_cnt[ei[E_ + e]], 1);
}

__global__ void scan1_kernel(int n) {
    __shared__ int s[1024];
    int i = blockIdx.x * 1024 + threadIdx.x;
    int v = (i < n) ? g_cnt[i] : 0;
    s[threadIdx.x] = v;
    __syncthreads();
#pragma unroll
    for (int off = 1; off < 1024; off <<= 1) {
        int t = (threadIdx.x >= off) ? s[threadIdx.x - off] : 0;
        __syncthreads();
        s[threadIdx.x] += t;
        __syncthreads();
    }
    if (i < n) g_rowstart[i] = s[threadIdx.x] - v;
    if (threadIdx.x == 1023) g_bsum[blockIdx.x] = s[1023];
}

__global__ void scan2_kernel(int nb, int n) {
    if (threadIdx.x == 0) {
        int acc = 0;
        for (int b = 0; b < nb; b++) {
            int t = g_bsum[b];
            g_bsum[b] = acc;
            acc += t;
        }
        g_rowstart[n] = acc;
    }
}

__global__ void scan3_kernel(int n) {
    int i = blockIdx.x * blockDim.x + threadIdx.x;
    if (i < n) g_rowstart[i] += g_bsum[i >> 10];
}

__global__ void fill_kernel(const int* __restrict__ ei, int E_) {
    int e = blockIdx.x * blockDim.x + threadIdx.x;
    if (e >= E_) return;
    int dst = ei[E_ + e];
    int pos = atomicAdd(&g_fill[dst], 1);
    g_srcsorted[g_rowstart[dst] + pos] = ei[e];
}

// ================= aggregate: warp per dst node, fp16 gather =================
__global__ __launch_bounds__(256) void aggregate_kernel(int n) {
    int w = (blockIdx.x * blockDim.x + threadIdx.x) >> 5;
    if (w >= n) return;
    int lane = threadIdx.x & 31;
    int beg = g_rowstart[w];
    int end = g_rowstart[w + 1];

    float4 acc = make_float4(0.f, 0.f, 0.f, 0.f);
    int i = beg;
    for (; i + 4 <= end; i += 4) {
        int s0 = g_srcsorted[i];
        int s1 = g_srcsorted[i + 1];
        int s2 = g_srcsorted[i + 2];
        int s3 = g_srcsorted[i + 3];
        uint2 r0 = *(const uint2*)&g_feat16[(size_t)s0 * 64 + lane * 2];
        uint2 r1 = *(const uint2*)&g_feat16[(size_t)s1 * 64 + lane * 2];
        uint2 r2 = *(const uint2*)&g_feat16[(size_t)s2 * 64 + lane * 2];
        uint2 r3 = *(const uint2*)&g_feat16[(size_t)s3 * 64 + lane * 2];
        float2 a0 = __half22float2(*(__half2*)&r0.x), b0 = __half22float2(*(__half2*)&r0.y);
        float2 a1 = __half22float2(*(__half2*)&r1.x), b1 = __half22float2(*(__half2*)&r1.y);
        float2 a2 = __half22float2(*(__half2*)&r2.x), b2 = __half22float2(*(__half2*)&r2.y);
        float2 a3 = __half22float2(*(__half2*)&r3.x), b3 = __half22float2(*(__half2*)&r3.y);
        acc.x += (a0.x + a1.x) + (a2.x + a3.x);
        acc.y += (a0.y + a1.y) + (a2.y + a3.y);
        acc.z += (b0.x + b1.x) + (b2.x + b3.x);
        acc.w += (b0.y + b1.y) + (b2.y + b3.y);
    }
    for (; i < end; i++) {
        int s0 = g_srcsorted[i];
        uint2 r0 = *(const uint2*)&g_feat16[(size_t)s0 * 64 + lane * 2];
        float2 a0 = __half22float2(*(__half2*)&r0.x), b0 = __half22float2(*(__half2*)&r0.y);
        acc.x += a0.x;
        acc.y += a0.y;
        acc.z += b0.x;
        acc.w += b0.y;
    }
    float inv = 1.0f / fmaxf((float)(end - beg), 1.0f);
    acc.x *= inv;
    acc.y *= inv;
    acc.z *= inv;
    acc.w *= inv;
    *(float4*)&g_msg[w * HID + lane * 4] = acc;
}

// ================= launch =================
extern "C" void kernel_launch(void* const* d_in, const int* in_sizes, int n_in,
                              void* d_out, int out_size) {
    const float* x   = (const float*)d_in[0];
    const int*   ei  = (const int*)d_in[1];
    const float* W1  = (const float*)d_in[2];
    const float* b1  = (const float*)d_in[3];
    const float* g1  = (const float*)d_in[4];
    const float* be1 = (const float*)d_in[5];
    const float* Wl  = (const float*)d_in[6];
    const float* bl  = (const float*)d_in[7];
    const float* Wr  = (const float*)d_in[8];
    const float* g2  = (const float*)d_in[9];
    const float* be2 = (const float*)d_in[10];

    int n  = in_sizes[0] / D_IN;
    int E_ = in_sizes[1] / 2;

    float* feat = (float*)d_out;
    float* out2 = feat + (size_t)n * HID;

    int n4 = n * (HID / 4);
    int eblocks = (E_ + 255) / 256;
    int nblocks = (n + 255) / 256;
    int nb1024 = (n + 1023) / 1024;
    int tblocks = (n + 127) / 128;

    static int smem_set = 0;
    if (!smem_set) {
        cudaFuncSetAttribute(tc_gemm_kernel,
                             cudaFuncAttributeMaxDynamicSharedMemorySize, SM_GTOTAL);
        smem_set = 1;
    }

    // launch order keeps tc_gemm mode0 at index 3 (profiled slot)
    zero_kernel<<<nblocks, 256>>>(n);                                  // 0
    wprep_kernel<<<(2 * 256 * 128 + 255) / 256, 256>>>(W1, Wl, Wr);    // 1
    count_kernel<<<eblocks, 256>>>(ei, E_);                            // 2
    tc_gemm_kernel<<<tblocks, 256, SM_GTOTAL>>>(0, x, b1, n);          // 3 (profiled)
    bn_finalize_kernel<<<1, HID>>>(g1, be1, n, 0);                     // 4
    bn_apply_kernel<<<(n4 + 255) / 256, 256>>>(0, feat, n4, 0, 1);     // 5
    scan1_kernel<<<nb1024, 1024>>>(n);
    scan2_kernel<<<1, 32>>>(nb1024, n);
    scan3_kernel<<<nblocks, 256>>>(n);
    fill_kernel<<<eblocks, 256>>>(ei, E_);
    aggregate_kernel<<<(n * 32 + 255) / 256, 256>>>(n);
    tc_gemm_kernel<<<tblocks, 256, SM_GTOTAL>>>(1, nullptr, bl, n);
    bn_finalize_kernel<<<1, HID>>>(g2, be2, n, 1);
    bn_apply_kernel<<<(n4 + 255) / 256, 256>>>(1, out2, n4, 1, 0);
}